// round 3
// baseline (speedup 1.0000x reference)
#include <cuda_runtime.h>

// ---------------- problem constants (fixed for this dataset) ----------------
#define D_    128
#define DA_   64
#define DB_   8
#define NR_   6
#define NS_   42
#define E_MAX 200000
#define T_MAX 1600000

// ---------------- scratch (static device globals; no allocation) ------------
__device__ __align__(16) float g_t1  [(size_t)E_MAX * D_];   // 102.4 MB
__device__ __align__(16) float g_mbuf[(size_t)E_MAX * D_];   // 102.4 MB
__device__ __align__(16) float g_down[(size_t)E_MAX * DA_];  // 51.2 MB
__device__ __align__(16) float g_agg [(size_t)E_MAX * DA_];  // 51.2 MB
__device__ __align__(16) float g_hrbf[(size_t)E_MAX * DB_];  // 6.4 MB
__device__ __align__(16) float g_hsbf[(size_t)T_MAX * DB_];  // 51.2 MB

// ---------------- helpers ----------------------------------------------------
typedef unsigned long long ull;

__device__ __forceinline__ ull splat2(float a) {
    ull r;
    asm("mov.b64 %0, {%1, %1};" : "=l"(r) : "f"(a));
    return r;
}
__device__ __forceinline__ void pfma(ull& c, ull a, ull b) {
    asm("fma.rn.f32x2 %0, %1, %2, %0;" : "+l"(c) : "l"(a), "l"(b));
}
__device__ __forceinline__ float2 u2f2(ull u) {
    float2 f;
    asm("mov.b64 {%0, %1}, %2;" : "=f"(f.x), "=f"(f.y) : "l"(u));
    return f;
}
__device__ __forceinline__ float silu_f(float x) {
    return x / (1.0f + __expf(-x));
}

// ---------------- epilogue modes ---------------------------------------------
#define EP_SILU        0   // out = silu(acc + bias)
#define EP_SILU_ADD    1   // out = silu(acc + bias) + res[r][c]
#define EP_SILU_MULRBF 2   // out = silu(acc + bias) * ((hrbf[r] @ Wrbf2)[c])

// ---------------- fused GEMM: out = epi(A[E,KDIM] @ W[KDIM,NT]) ---------------
// Tile: 128 rows x NT cols, BK=16 K-slab, 256 threads, 8 cols/thread,
// BM/ (256/(NT/8)) rows/thread. Packed f32x2 FMA mainloop.
template <int KDIM, int NT, int MODE>
__global__ void __launch_bounds__(256) gemm_fused(
    const float* __restrict__ A, const float* __restrict__ W,
    const float* __restrict__ bias, const float* __restrict__ res,
    const float* __restrict__ hrbf, const float* __restrict__ wrbf2,
    float* __restrict__ out, int E)
{
    constexpr int BM  = 128;
    constexpr int BK  = 16;
    constexpr int TX  = NT / 8;          // 16 (NT=128) or 8 (NT=64)
    constexpr int TY  = 256 / TX;        // 16 or 32
    constexpr int RPT = BM / TY;         // 8 or 4 rows per thread
    constexpr int AF4 = (BM * BK) / (4 * 256);  // 2
    constexpr int WF4 = (BK * NT) / (4 * 256);  // 2 or 1
    constexpr int NK  = KDIM / BK;       // 8 or 4

    __shared__ float sA[2][BK][BM];
    __shared__ float sB[2][BK][NT];
    __shared__ float sBias[NT];
    __shared__ float sW2[(MODE == EP_SILU_MULRBF) ? (DB_ * NT) : 4];

    const int tid = threadIdx.x;
    const int tx  = tid % TX;
    const int ty  = tid / TX;
    const int rowBase = blockIdx.x * BM;

    if (tid < NT) sBias[tid] = bias ? bias[tid] : 0.0f;
    if (MODE == EP_SILU_MULRBF) {
        for (int i = tid; i < DB_ * NT; i += 256) sW2[i] = wrbf2[i];
    }

    float4 ra[AF4];
    float4 rw[WF4];

    auto loadTiles = [&](int ks) {
#pragma unroll
        for (int i = 0; i < AF4; i++) {
            int f  = tid + i * 256;      // float4 index within A tile
            int r  = f >> 2;             // BK/4 = 4 float4 per row
            int c4 = f & 3;
            int grow = rowBase + r;
            if (grow < E)
                ra[i] = __ldg((const float4*)(A + (size_t)grow * KDIM + ks * BK + c4 * 4));
            else
                ra[i] = make_float4(0.f, 0.f, 0.f, 0.f);
        }
#pragma unroll
        for (int i = 0; i < WF4; i++) {
            int f  = tid + i * 256;
            int kr = f / (NT / 4);
            int c4 = f % (NT / 4);
            rw[i] = __ldg((const float4*)(W + (size_t)(ks * BK + kr) * NT + c4 * 4));
        }
    };
    auto storeTiles = [&](int buf) {
#pragma unroll
        for (int i = 0; i < AF4; i++) {
            int f  = tid + i * 256;
            int r  = f >> 2;
            int c4 = f & 3;
            sA[buf][c4 * 4 + 0][r] = ra[i].x;
            sA[buf][c4 * 4 + 1][r] = ra[i].y;
            sA[buf][c4 * 4 + 2][r] = ra[i].z;
            sA[buf][c4 * 4 + 3][r] = ra[i].w;
        }
#pragma unroll
        for (int i = 0; i < WF4; i++) {
            int f  = tid + i * 256;
            int kr = f / (NT / 4);
            int c4 = f % (NT / 4);
            *(float4*)&sB[buf][kr][c4 * 4] = rw[i];
        }
    };

    ull acc[RPT][4];
#pragma unroll
    for (int r = 0; r < RPT; r++)
#pragma unroll
        for (int j = 0; j < 4; j++) acc[r][j] = 0ULL;

    loadTiles(0);
    storeTiles(0);
    __syncthreads();

    for (int ks = 0; ks < NK; ks++) {
        const int cur = ks & 1;
        const int nxt = cur ^ 1;
        if (ks + 1 < NK) loadTiles(ks + 1);
#pragma unroll
        for (int kk = 0; kk < BK; kk++) {
            ull b2[4];
            const ull* bp = reinterpret_cast<const ull*>(&sB[cur][kk][tx * 8]);
#pragma unroll
            for (int j = 0; j < 4; j++) b2[j] = bp[j];

            float as[RPT];
            const float4* ap = (const float4*)&sA[cur][kk][ty * RPT];
#pragma unroll
            for (int rv = 0; rv < RPT / 4; rv++) {
                float4 t = ap[rv];
                as[rv * 4 + 0] = t.x; as[rv * 4 + 1] = t.y;
                as[rv * 4 + 2] = t.z; as[rv * 4 + 3] = t.w;
            }
#pragma unroll
            for (int r = 0; r < RPT; r++) {
                ull a2 = splat2(as[r]);
#pragma unroll
                for (int j = 0; j < 4; j++) pfma(acc[r][j], a2, b2[j]);
            }
        }
        __syncthreads();
        if (ks + 1 < NK) {
            storeTiles(nxt);
            __syncthreads();
        }
    }

    // --------- epilogue ---------
    const int c0 = tx * 8;
#pragma unroll
    for (int r = 0; r < RPT; r++) {
        int grow = rowBase + ty * RPT + r;
        if (grow >= E) continue;

        float v[8];
#pragma unroll
        for (int j = 0; j < 4; j++) {
            float2 f = u2f2(acc[r][j]);
            v[2 * j] = f.x; v[2 * j + 1] = f.y;
        }

        float hh[8];
        if (MODE == EP_SILU_MULRBF) {
            const float4* hp = (const float4*)(hrbf + (size_t)grow * DB_);
            float4 h0 = __ldg(hp), h1 = __ldg(hp + 1);
            hh[0] = h0.x; hh[1] = h0.y; hh[2] = h0.z; hh[3] = h0.w;
            hh[4] = h1.x; hh[5] = h1.y; hh[6] = h1.z; hh[7] = h1.w;
        }
        float rr[8];
        if (MODE == EP_SILU_ADD) {
            const float4* rp = (const float4*)(res + (size_t)grow * NT + c0);
            float4 r0 = __ldg(rp), r1 = __ldg(rp + 1);
            rr[0] = r0.x; rr[1] = r0.y; rr[2] = r0.z; rr[3] = r0.w;
            rr[4] = r1.x; rr[5] = r1.y; rr[6] = r1.z; rr[7] = r1.w;
        }

        float o[8];
#pragma unroll
        for (int c = 0; c < 8; c++) {
            float x = v[c] + sBias[c0 + c];
            float s = silu_f(x);
            if (MODE == EP_SILU) {
                o[c] = s;
            } else if (MODE == EP_SILU_ADD) {
                o[c] = s + rr[c];
            } else {  // EP_SILU_MULRBF
                float rp2 = 0.0f;
#pragma unroll
                for (int j = 0; j < DB_; j++) rp2 += hh[j] * sW2[j * NT + c0 + c];
                o[c] = s * rp2;
            }
        }
        float4* op = (float4*)(out + (size_t)grow * NT + c0);
        op[0] = make_float4(o[0], o[1], o[2], o[3]);
        op[1] = make_float4(o[4], o[5], o[6], o[7]);
    }
}

// ---------------- small kernels -----------------------------------------------
__global__ void __launch_bounds__(256) k_zero(float4* __restrict__ p, int n4) {
    int i = blockIdx.x * blockDim.x + threadIdx.x;
    if (i < n4) p[i] = make_float4(0.f, 0.f, 0.f, 0.f);
}

// h_rbf[E,8] = rbf[E,6] @ Wrbf1[6,8]
__global__ void __launch_bounds__(256) k_hrbf(
    const float* __restrict__ rbf, const float* __restrict__ w1,
    float* __restrict__ out, int E)
{
    __shared__ float sw[NR_ * DB_];
    if (threadIdx.x < NR_ * DB_) sw[threadIdx.x] = w1[threadIdx.x];
    __syncthreads();
    int r = blockIdx.x * blockDim.x + threadIdx.x;
    if (r >= E) return;
    float x[NR_];
#pragma unroll
    for (int j = 0; j < NR_; j++) x[j] = __ldg(rbf + (size_t)r * NR_ + j);
    float h[DB_];
#pragma unroll
    for (int k = 0; k < DB_; k++) h[k] = 0.f;
#pragma unroll
    for (int j = 0; j < NR_; j++)
#pragma unroll
        for (int k = 0; k < DB_; k++) h[k] += x[j] * sw[j * DB_ + k];
    float4* op = (float4*)(out + (size_t)r * DB_);
    op[0] = make_float4(h[0], h[1], h[2], h[3]);
    op[1] = make_float4(h[4], h[5], h[6], h[7]);
}

// h_sbf[T,8] = sbf[T,42] @ Wsbf1[42,8]   (staged through shared for coalescing)
__global__ void __launch_bounds__(256) k_hsbf(
    const float* __restrict__ sbf, const float* __restrict__ w1,
    float* __restrict__ out, int T)
{
    __shared__ float st[256 * NS_];
    __shared__ float sw[NS_ * DB_];
    for (int i = threadIdx.x; i < NS_ * DB_; i += 256) sw[i] = w1[i];

    int base = blockIdx.x * 256;
    int n = T - base; if (n > 256) n = 256;
    int total = n * NS_;
    for (int i = threadIdx.x; i < total; i += 256)
        st[i] = sbf[(size_t)base * NS_ + i];
    __syncthreads();

    int r = threadIdx.x;
    if (r >= n) return;
    const float* x = &st[r * NS_];
    float h[DB_];
#pragma unroll
    for (int k = 0; k < DB_; k++) h[k] = 0.f;
#pragma unroll
    for (int j = 0; j < NS_; j++) {
        float xv = x[j];
#pragma unroll
        for (int k = 0; k < DB_; k++) h[k] += xv * sw[j * DB_ + k];
    }
    float4* op = (float4*)(out + (size_t)(base + r) * DB_);
    op[0] = make_float4(h[0], h[1], h[2], h[3]);
    op[1] = make_float4(h[4], h[5], h[6], h[7]);
}

// Triplet: agg[reduce_to_ji[t]] += down[expand_to_kj[t]] * (h_sbf[t] @ Wsbf2)
// 16 threads per triplet, 4 cols per thread, vectorized red.global.add.v4.f32.
__global__ void __launch_bounds__(256) k_triplet(
    const float* __restrict__ hsbf, const float* __restrict__ wsbf2,
    const int* __restrict__ exp_kj, const int* __restrict__ red_ji,
    const float* __restrict__ down, float* __restrict__ agg, int T)
{
    __shared__ float sw[DB_ * DA_];
    for (int i = threadIdx.x; i < DB_ * DA_; i += 256) sw[i] = wsbf2[i];
    __syncthreads();

    const int q = threadIdx.x & 15;
    float w[DB_][4];
#pragma unroll
    for (int i = 0; i < DB_; i++)
#pragma unroll
        for (int j = 0; j < 4; j++) w[i][j] = sw[i * DA_ + q * 4 + j];

    int t = (blockIdx.x * blockDim.x + threadIdx.x) >> 4;
    const int stride = (gridDim.x * blockDim.x) >> 4;

    for (; t < T; t += stride) {
        int e = __ldg(exp_kj + t);
        int g = __ldg(red_ji + t);
        const float4* hp = (const float4*)(hsbf + (size_t)t * DB_);
        float4 h0 = __ldg(hp), h1 = __ldg(hp + 1);
        float hh[8] = {h0.x, h0.y, h0.z, h0.w, h1.x, h1.y, h1.z, h1.w};

        float s0 = 0.f, s1 = 0.f, s2 = 0.f, s3 = 0.f;
#pragma unroll
        for (int i = 0; i < DB_; i++) {
            s0 += hh[i] * w[i][0];
            s1 += hh[i] * w[i][1];
            s2 += hh[i] * w[i][2];
            s3 += hh[i] * w[i][3];
        }
        float4 a = __ldg((const float4*)(down + (size_t)e * DA_ + q * 4));
        float vx = a.x * s0, vy = a.y * s1, vz = a.z * s2, vw = a.w * s3;

        float* dst = agg + (size_t)g * DA_ + q * 4;
        asm volatile("red.global.add.v4.f32 [%0], {%1, %2, %3, %4};"
                     :: "l"(dst), "f"(vx), "f"(vy), "f"(vz), "f"(vw)
                     : "memory");
    }
}

// ---------------- launch -------------------------------------------------------
extern "C" void kernel_launch(void* const* d_in, const int* in_sizes, int n_in,
                              void* d_out, int out_size)
{
    const float* m_input  = (const float*)d_in[0];
    const float* rbf      = (const float*)d_in[1];
    const float* sbf      = (const float*)d_in[2];
    const float* Wkj      = (const float*)d_in[3];
    const float* bkj      = (const float*)d_in[4];
    const float* Wrbf1    = (const float*)d_in[5];
    const float* Wrbf2    = (const float*)d_in[6];
    const float* Wdown    = (const float*)d_in[7];
    const float* Wsbf1    = (const float*)d_in[8];
    const float* Wsbf2    = (const float*)d_in[9];
    const float* Wup      = (const float*)d_in[10];
    const float* Wji      = (const float*)d_in[11];
    const float* bji      = (const float*)d_in[12];
    const float* rb1_W1   = (const float*)d_in[13];
    const float* rb1_b1   = (const float*)d_in[14];
    const float* rb1_W2   = (const float*)d_in[15];
    const float* rb1_b2   = (const float*)d_in[16];
    const float* Wfin     = (const float*)d_in[17];
    const float* bfin     = (const float*)d_in[18];
    const float* ra1_W1   = (const float*)d_in[19];
    const float* ra1_b1   = (const float*)d_in[20];
    const float* ra1_W2   = (const float*)d_in[21];
    const float* ra1_b2   = (const float*)d_in[22];
    const float* ra2_W1   = (const float*)d_in[23];
    const float* ra2_b1   = (const float*)d_in[24];
    const float* ra2_W2   = (const float*)d_in[25];
    const float* ra2_b2   = (const float*)d_in[26];
    const int*   red_ji   = (const int*)  d_in[27];
    const int*   exp_kj   = (const int*)  d_in[28];

    const int E = in_sizes[0] / D_;
    const int T = in_sizes[27];

    float *t1, *m, *down, *agg, *hrbf, *hsbf;
    cudaGetSymbolAddress((void**)&t1,   g_t1);
    cudaGetSymbolAddress((void**)&m,    g_mbuf);
    cudaGetSymbolAddress((void**)&down, g_down);
    cudaGetSymbolAddress((void**)&agg,  g_agg);
    cudaGetSymbolAddress((void**)&hrbf, g_hrbf);
    cudaGetSymbolAddress((void**)&hsbf, g_hsbf);

    float* outp = (float*)d_out;
    const int grid = (E + 127) / 128;

    // 1. zero aggregation buffer
    {
        int n4 = (E * DA_) / 4;
        k_zero<<<(n4 + 255) / 256, 256>>>((float4*)agg, n4);
    }
    // 2-3. small basis projections
    k_hrbf<<<(E + 255) / 256, 256>>>(rbf, Wrbf1, hrbf, E);
    k_hsbf<<<(T + 255) / 256, 256>>>(sbf, Wsbf1, hsbf, T);

    // 4. m_ang = silu(m_input @ Wkj + bkj) * (h_rbf @ Wrbf2)      -> t1 [E,128]
    gemm_fused<128, 128, EP_SILU_MULRBF><<<grid, 256>>>(
        m_input, Wkj, bkj, nullptr, hrbf, Wrbf2, t1, E);
    // 5. down = silu(t1 @ Wdown)                                  -> down [E,64]
    gemm_fused<128, 64, EP_SILU><<<grid, 256>>>(
        t1, Wdown, nullptr, nullptr, nullptr, nullptr, down, E);
    // 6. triplet gather / sbf-mod / scatter-add                   -> agg [E,64]
    k_triplet<<<2048, 256>>>(hsbf, Wsbf2, exp_kj, red_ji, down, agg, T);
    // 7. prop = silu(agg @ Wup)                                   -> t1 [E,128]
    gemm_fused<64, 128, EP_SILU><<<grid, 256>>>(
        agg, Wup, nullptr, nullptr, nullptr, nullptr, t1, E);
    // 8. m = silu(m_input @ Wji + bji) + prop                     -> m
    gemm_fused<128, 128, EP_SILU_ADD><<<grid, 256>>>(
        m_input, Wji, bji, t1, nullptr, nullptr, m, E);
    // 9-10. residual block b1
    gemm_fused<128, 128, EP_SILU><<<grid, 256>>>(
        m, rb1_W1, rb1_b1, nullptr, nullptr, nullptr, t1, E);
    gemm_fused<128, 128, EP_SILU_ADD><<<grid, 256>>>(
        t1, rb1_W2, rb1_b2, m, nullptr, nullptr, m, E);
    // 11. m = silu(m @ Wfin + bfin) + m_input
    gemm_fused<128, 128, EP_SILU_ADD><<<grid, 256>>>(
        m, Wfin, bfin, m_input, nullptr, nullptr, m, E);
    // 12-13. residual block a1
    gemm_fused<128, 128, EP_SILU><<<grid, 256>>>(
        m, ra1_W1, ra1_b1, nullptr, nullptr, nullptr, t1, E);
    gemm_fused<128, 128, EP_SILU_ADD><<<grid, 256>>>(
        t1, ra1_W2, ra1_b2, m, nullptr, nullptr, m, E);
    // 14-15. residual block a2 -> final output
    gemm_fused<128, 128, EP_SILU><<<grid, 256>>>(
        m, ra2_W1, ra2_b1, nullptr, nullptr, nullptr, t1, E);
    gemm_fused<128, 128, EP_SILU_ADD><<<grid, 256>>>(
        t1, ra2_W2, ra2_b2, m, nullptr, nullptr, outp, E);
}

// round 5
// speedup vs baseline: 1.1482x; 1.1482x over previous
#include <cuda_runtime.h>

// ---------------- problem constants (fixed for this dataset) ----------------
#define D_    128
#define DA_   64
#define DB_   8
#define NR_   6
#define NS_   42
#define E_MAX 200000
#define T_MAX 1600000

// ---------------- scratch (static device globals; no allocation) ------------
__device__ __align__(16) float g_t1  [(size_t)E_MAX * D_];   // 102.4 MB
__device__ __align__(16) float g_mbuf[(size_t)E_MAX * D_];   // 102.4 MB
__device__ __align__(16) float g_down[(size_t)E_MAX * DA_];  // 51.2 MB
__device__ __align__(16) float g_agg [(size_t)E_MAX * DA_];  // 51.2 MB
__device__ __align__(16) float g_hrbf[(size_t)E_MAX * DB_];  // 6.4 MB
__device__ __align__(16) float g_hsbf[(size_t)T_MAX * DB_];  // 51.2 MB

// ---------------- helpers ----------------------------------------------------
typedef unsigned long long ull;

__device__ __forceinline__ ull splat2(float a) {
    ull r;
    asm("mov.b64 %0, {%1, %1};" : "=l"(r) : "f"(a));
    return r;
}
__device__ __forceinline__ void pfma(ull& c, ull a, ull b) {
    asm("fma.rn.f32x2 %0, %1, %2, %0;" : "+l"(c) : "l"(a), "l"(b));
}
__device__ __forceinline__ float2 u2f2(ull u) {
    float2 f;
    asm("mov.b64 {%0, %1}, %2;" : "=f"(f.x), "=f"(f.y) : "l"(u));
    return f;
}
__device__ __forceinline__ float silu_f(float x) {
    return x / (1.0f + __expf(-x));
}

// ---------------- epilogue modes ---------------------------------------------
#define EP_SILU        0   // out = silu(acc + bias)
#define EP_SILU_ADD    1   // out = silu(acc + bias) + res[r][c]
#define EP_SILU_MULRBF 2   // out = silu(acc + bias) * ((hrbf[r] @ Wrbf2)[c])

// ---------------- fused GEMM: out = epi(A[E,KDIM] @ W[KDIM,NT]) ---------------
// Tile: 128 rows x NT cols, BK=16 K-slab, 256 threads.
// Each thread: RPT rows x 8 cols, cols split as {tx*4..+3} U {NT/2+tx*4..+3}
// so B shared reads are conflict-free LDS.128 (quarter-warp hits banks 0,4..28).
// sA padded to 132 floats/row to tame transpose-store conflicts.
template <int KDIM, int NT, int MODE>
__global__ void __launch_bounds__(256, 2) gemm_fused(
    const float* __restrict__ A, const float* __restrict__ W,
    const float* __restrict__ bias, const float* __restrict__ res,
    const float* __restrict__ hrbf, const float* __restrict__ wrbf2,
    float* __restrict__ out, int E)
{
    constexpr int BM  = 128;
    constexpr int BMP = 132;                    // padded row (16B-aligned, kills 4-way STS conflict)
    constexpr int BK  = 16;
    constexpr int TX  = NT / 8;                 // 16 (NT=128) or 8 (NT=64)
    constexpr int TY  = 256 / TX;               // 16 or 32
    constexpr int RPT = BM / TY;                // 8 or 4 rows per thread
    constexpr int AF4 = (BM * BK) / (4 * 256);  // 2
    constexpr int WF4 = (BK * NT) / (4 * 256);  // 2 or 1
    constexpr int NK  = KDIM / BK;              // 8 or 4
    constexpr int HN  = NT / 2;

    __shared__ float sA[2][BK][BMP];
    __shared__ float sB[2][BK][NT];
    __shared__ float sBias[NT];
    __shared__ float sW2[(MODE == EP_SILU_MULRBF) ? (DB_ * NT) : 4];

    const int tid = threadIdx.x;
    const int tx  = tid % TX;
    const int ty  = tid / TX;
    const int rowBase = blockIdx.x * BM;

    if (tid < NT) sBias[tid] = bias ? bias[tid] : 0.0f;
    if (MODE == EP_SILU_MULRBF) {
        for (int i = tid; i < DB_ * NT; i += 256) sW2[i] = wrbf2[i];
    }

    float4 ra[AF4];
    float4 rw[WF4];

    auto loadTiles = [&](int ks) {
#pragma unroll
        for (int i = 0; i < AF4; i++) {
            int f  = tid + i * 256;      // float4 index within A tile
            int r  = f >> 2;             // BK/4 = 4 float4 per row
            int c4 = f & 3;
            int grow = rowBase + r;
            if (grow < E)
                ra[i] = __ldg((const float4*)(A + (size_t)grow * KDIM + ks * BK + c4 * 4));
            else
                ra[i] = make_float4(0.f, 0.f, 0.f, 0.f);
        }
#pragma unroll
        for (int i = 0; i < WF4; i++) {
            int f  = tid + i * 256;
            int kr = f / (NT / 4);
            int c4 = f % (NT / 4);
            rw[i] = __ldg((const float4*)(W + (size_t)(ks * BK + kr) * NT + c4 * 4));
        }
    };
    auto storeTiles = [&](int buf) {
#pragma unroll
        for (int i = 0; i < AF4; i++) {
            int f  = tid + i * 256;
            int r  = f >> 2;
            int c4 = f & 3;
            sA[buf][c4 * 4 + 0][r] = ra[i].x;
            sA[buf][c4 * 4 + 1][r] = ra[i].y;
            sA[buf][c4 * 4 + 2][r] = ra[i].z;
            sA[buf][c4 * 4 + 3][r] = ra[i].w;
        }
#pragma unroll
        for (int i = 0; i < WF4; i++) {
            int f  = tid + i * 256;
            int kr = f / (NT / 4);
            int c4 = f % (NT / 4);
            *(float4*)&sB[buf][kr][c4 * 4] = rw[i];
        }
    };

    // acc[r][0..1] -> cols tx*4..tx*4+3 ; acc[r][2..3] -> cols HN+tx*4..+3
    ull acc[RPT][4];
#pragma unroll
    for (int r = 0; r < RPT; r++)
#pragma unroll
        for (int j = 0; j < 4; j++) acc[r][j] = 0ULL;

    loadTiles(0);
    storeTiles(0);
    __syncthreads();

    for (int ks = 0; ks < NK; ks++) {
        const int cur = ks & 1;
        const int nxt = cur ^ 1;
        if (ks + 1 < NK) loadTiles(ks + 1);
#pragma unroll
        for (int kk = 0; kk < BK; kk++) {
            // conflict-free B reads: two LDS.128 per thread
            ull b2[4];
            {
                ulonglong2 b0 = *(const ulonglong2*)&sB[cur][kk][tx * 4];
                ulonglong2 b1 = *(const ulonglong2*)&sB[cur][kk][HN + tx * 4];
                b2[0] = b0.x; b2[1] = b0.y;
                b2[2] = b1.x; b2[3] = b1.y;
            }

            float as[RPT];
            const float4* ap = (const float4*)&sA[cur][kk][ty * RPT];
#pragma unroll
            for (int rv = 0; rv < RPT / 4; rv++) {
                float4 t = ap[rv];
                as[rv * 4 + 0] = t.x; as[rv * 4 + 1] = t.y;
                as[rv * 4 + 2] = t.z; as[rv * 4 + 3] = t.w;
            }
#pragma unroll
            for (int r = 0; r < RPT; r++) {
                ull a2 = splat2(as[r]);
#pragma unroll
                for (int j = 0; j < 4; j++) pfma(acc[r][j], a2, b2[j]);
            }
        }
        __syncthreads();
        if (ks + 1 < NK) {
            storeTiles(nxt);
            __syncthreads();
        }
    }

    // --------- epilogue ---------
    const int c0a = tx * 4;
    const int c0b = HN + tx * 4;
#pragma unroll
    for (int r = 0; r < RPT; r++) {
        int grow = rowBase + ty * RPT + r;
        if (grow >= E) continue;

        float v[8];
#pragma unroll
        for (int j = 0; j < 4; j++) {
            float2 f = u2f2(acc[r][j]);
            v[2 * j] = f.x; v[2 * j + 1] = f.y;
        }
        // v[0..3] -> cols c0a..c0a+3 ; v[4..7] -> cols c0b..c0b+3

        float hh[8];
        if (MODE == EP_SILU_MULRBF) {
            const float4* hp = (const float4*)(hrbf + (size_t)grow * DB_);
            float4 h0 = __ldg(hp), h1 = __ldg(hp + 1);
            hh[0] = h0.x; hh[1] = h0.y; hh[2] = h0.z; hh[3] = h0.w;
            hh[4] = h1.x; hh[5] = h1.y; hh[6] = h1.z; hh[7] = h1.w;
        }
        float rr[8];
        if (MODE == EP_SILU_ADD) {
            const float4* rpA = (const float4*)(res + (size_t)grow * NT + c0a);
            const float4* rpB = (const float4*)(res + (size_t)grow * NT + c0b);
            float4 r0 = __ldg(rpA), r1 = __ldg(rpB);
            rr[0] = r0.x; rr[1] = r0.y; rr[2] = r0.z; rr[3] = r0.w;
            rr[4] = r1.x; rr[5] = r1.y; rr[6] = r1.z; rr[7] = r1.w;
        }

        float o[8];
#pragma unroll
        for (int c = 0; c < 8; c++) {
            const int col = (c < 4) ? (c0a + c) : (c0b + c - 4);
            float x = v[c] + sBias[col];
            float s = silu_f(x);
            if (MODE == EP_SILU) {
                o[c] = s;
            } else if (MODE == EP_SILU_ADD) {
                o[c] = s + rr[c];
            } else {  // EP_SILU_MULRBF
                float rp2 = 0.0f;
#pragma unroll
                for (int j = 0; j < DB_; j++) rp2 += hh[j] * sW2[j * NT + col];
                o[c] = s * rp2;
            }
        }
        *(float4*)(out + (size_t)grow * NT + c0a) = make_float4(o[0], o[1], o[2], o[3]);
        *(float4*)(out + (size_t)grow * NT + c0b) = make_float4(o[4], o[5], o[6], o[7]);
    }
}

// ---------------- small kernels -----------------------------------------------
__global__ void __launch_bounds__(256) k_zero(float4* __restrict__ p, int n4) {
    int i = blockIdx.x * blockDim.x + threadIdx.x;
    if (i < n4) p[i] = make_float4(0.f, 0.f, 0.f, 0.f);
}

// h_rbf[E,8] = rbf[E,6] @ Wrbf1[6,8]
__global__ void __launch_bounds__(256) k_hrbf(
    const float* __restrict__ rbf, const float* __restrict__ w1,
    float* __restrict__ out, int E)
{
    __shared__ float sw[NR_ * DB_];
    if (threadIdx.x < NR_ * DB_) sw[threadIdx.x] = w1[threadIdx.x];
    __syncthreads();
    int r = blockIdx.x * blockDim.x + threadIdx.x;
    if (r >= E) return;
    float x[NR_];
#pragma unroll
    for (int j = 0; j < NR_; j++) x[j] = __ldg(rbf + (size_t)r * NR_ + j);
    float h[DB_];
#pragma unroll
    for (int k = 0; k < DB_; k++) h[k] = 0.f;
#pragma unroll
    for (int j = 0; j < NR_; j++)
#pragma unroll
        for (int k = 0; k < DB_; k++) h[k] += x[j] * sw[j * DB_ + k];
    float4* op = (float4*)(out + (size_t)r * DB_);
    op[0] = make_float4(h[0], h[1], h[2], h[3]);
    op[1] = make_float4(h[4], h[5], h[6], h[7]);
}

// h_sbf[T,8] = sbf[T,42] @ Wsbf1[42,8]   (staged through shared for coalescing)
__global__ void __launch_bounds__(256) k_hsbf(
    const float* __restrict__ sbf, const float* __restrict__ w1,
    float* __restrict__ out, int T)
{
    __shared__ float st[256 * NS_];
    __shared__ float sw[NS_ * DB_];
    for (int i = threadIdx.x; i < NS_ * DB_; i += 256) sw[i] = w1[i];

    int base = blockIdx.x * 256;
    int n = T - base; if (n > 256) n = 256;
    int total = n * NS_;
    for (int i = threadIdx.x; i < total; i += 256)
        st[i] = sbf[(size_t)base * NS_ + i];
    __syncthreads();

    int r = threadIdx.x;
    if (r >= n) return;
    const float* x = &st[r * NS_];
    float h[DB_];
#pragma unroll
    for (int k = 0; k < DB_; k++) h[k] = 0.f;
#pragma unroll
    for (int j = 0; j < NS_; j++) {
        float xv = x[j];
#pragma unroll
        for (int k = 0; k < DB_; k++) h[k] += xv * sw[j * DB_ + k];
    }
    float4* op = (float4*)(out + (size_t)(base + r) * DB_);
    op[0] = make_float4(h[0], h[1], h[2], h[3]);
    op[1] = make_float4(h[4], h[5], h[6], h[7]);
}

// Triplet: agg[reduce_to_ji[t]] += down[expand_to_kj[t]] * (h_sbf[t] @ Wsbf2)
// 16 threads per triplet, 4 cols per thread, vectorized red.global.add.v4.f32.
__global__ void __launch_bounds__(256) k_triplet(
    const float* __restrict__ hsbf, const float* __restrict__ wsbf2,
    const int* __restrict__ exp_kj, const int* __restrict__ red_ji,
    const float* __restrict__ down, float* __restrict__ agg, int T)
{
    __shared__ float sw[DB_ * DA_];
    for (int i = threadIdx.x; i < DB_ * DA_; i += 256) sw[i] = wsbf2[i];
    __syncthreads();

    const int q = threadIdx.x & 15;
    float w[DB_][4];
#pragma unroll
    for (int i = 0; i < DB_; i++)
#pragma unroll
        for (int j = 0; j < 4; j++) w[i][j] = sw[i * DA_ + q * 4 + j];

    int t = (blockIdx.x * blockDim.x + threadIdx.x) >> 4;
    const int stride = (gridDim.x * blockDim.x) >> 4;

    for (; t < T; t += stride) {
        int e = __ldg(exp_kj + t);
        int g = __ldg(red_ji + t);
        const float4* hp = (const float4*)(hsbf + (size_t)t * DB_);
        float4 h0 = __ldg(hp), h1 = __ldg(hp + 1);
        float hh[8] = {h0.x, h0.y, h0.z, h0.w, h1.x, h1.y, h1.z, h1.w};

        float s0 = 0.f, s1 = 0.f, s2 = 0.f, s3 = 0.f;
#pragma unroll
        for (int i = 0; i < DB_; i++) {
            s0 += hh[i] * w[i][0];
            s1 += hh[i] * w[i][1];
            s2 += hh[i] * w[i][2];
            s3 += hh[i] * w[i][3];
        }
        float4 a = __ldg((const float4*)(down + (size_t)e * DA_ + q * 4));
        float vx = a.x * s0, vy = a.y * s1, vz = a.z * s2, vw = a.w * s3;

        float* dst = agg + (size_t)g * DA_ + q * 4;
        asm volatile("red.global.add.v4.f32 [%0], {%1, %2, %3, %4};"
                     :: "l"(dst), "f"(vx), "f"(vy), "f"(vz), "f"(vw)
                     : "memory");
    }
}

// ---------------- launch -------------------------------------------------------
extern "C" void kernel_launch(void* const* d_in, const int* in_sizes, int n_in,
                              void* d_out, int out_size)
{
    const float* m_input  = (const float*)d_in[0];
    const float* rbf      = (const float*)d_in[1];
    const float* sbf      = (const float*)d_in[2];
    const float* Wkj      = (const float*)d_in[3];
    const float* bkj      = (const float*)d_in[4];
    const float* Wrbf1    = (const float*)d_in[5];
    const float* Wrbf2    = (const float*)d_in[6];
    const float* Wdown    = (const float*)d_in[7];
    const float* Wsbf1    = (const float*)d_in[8];
    const float* Wsbf2    = (const float*)d_in[9];
    const float* Wup      = (const float*)d_in[10];
    const float* Wji      = (const float*)d_in[11];
    const float* bji      = (const float*)d_in[12];
    const float* rb1_W1   = (const float*)d_in[13];
    const float* rb1_b1   = (const float*)d_in[14];
    const float* rb1_W2   = (const float*)d_in[15];
    const float* rb1_b2   = (const float*)d_in[16];
    const float* Wfin     = (const float*)d_in[17];
    const float* bfin     = (const float*)d_in[18];
    const float* ra1_W1   = (const float*)d_in[19];
    const float* ra1_b1   = (const float*)d_in[20];
    const float* ra1_W2   = (const float*)d_in[21];
    const float* ra1_b2   = (const float*)d_in[22];
    const float* ra2_W1   = (const float*)d_in[23];
    const float* ra2_b1   = (const float*)d_in[24];
    const float* ra2_W2   = (const float*)d_in[25];
    const float* ra2_b2   = (const float*)d_in[26];
    const int*   red_ji   = (const int*)  d_in[27];
    const int*   exp_kj   = (const int*)  d_in[28];

    const int E = in_sizes[0] / D_;
    const int T = in_sizes[27];

    float *t1, *m, *down, *agg, *hrbf, *hsbf;
    cudaGetSymbolAddress((void**)&t1,   g_t1);
    cudaGetSymbolAddress((void**)&m,    g_mbuf);
    cudaGetSymbolAddress((void**)&down, g_down);
    cudaGetSymbolAddress((void**)&agg,  g_agg);
    cudaGetSymbolAddress((void**)&hrbf, g_hrbf);
    cudaGetSymbolAddress((void**)&hsbf, g_hsbf);

    float* outp = (float*)d_out;
    const int grid = (E + 127) / 128;

    // 1. zero aggregation buffer
    {
        int n4 = (E * DA_) / 4;
        k_zero<<<(n4 + 255) / 256, 256>>>((float4*)agg, n4);
    }
    // 2-3. small basis projections
    k_hrbf<<<(E + 255) / 256, 256>>>(rbf, Wrbf1, hrbf, E);
    k_hsbf<<<(T + 255) / 256, 256>>>(sbf, Wsbf1, hsbf, T);

    // 4. m_ang = silu(m_input @ Wkj + bkj) * (h_rbf @ Wrbf2)      -> t1 [E,128]
    gemm_fused<128, 128, EP_SILU_MULRBF><<<grid, 256>>>(
        m_input, Wkj, bkj, nullptr, hrbf, Wrbf2, t1, E);
    // 5. down = silu(t1 @ Wdown)                                  -> down [E,64]
    gemm_fused<128, 64, EP_SILU><<<grid, 256>>>(
        t1, Wdown, nullptr, nullptr, nullptr, nullptr, down, E);
    // 6. triplet gather / sbf-mod / scatter-add                   -> agg [E,64]
    k_triplet<<<2048, 256>>>(hsbf, Wsbf2, exp_kj, red_ji, down, agg, T);
    // 7. prop = silu(agg @ Wup)                                   -> t1 [E,128]
    gemm_fused<64, 128, EP_SILU><<<grid, 256>>>(
        agg, Wup, nullptr, nullptr, nullptr, nullptr, t1, E);
    // 8. m = silu(m_input @ Wji + bji) + prop                     -> m
    gemm_fused<128, 128, EP_SILU_ADD><<<grid, 256>>>(
        m_input, Wji, bji, t1, nullptr, nullptr, m, E);
    // 9-10. residual block b1
    gemm_fused<128, 128, EP_SILU><<<grid, 256>>>(
        m, rb1_W1, rb1_b1, nullptr, nullptr, nullptr, t1, E);
    gemm_fused<128, 128, EP_SILU_ADD><<<grid, 256>>>(
        t1, rb1_W2, rb1_b2, m, nullptr, nullptr, m, E);
    // 11. m = silu(m @ Wfin + bfin) + m_input
    gemm_fused<128, 128, EP_SILU_ADD><<<grid, 256>>>(
        m, Wfin, bfin, m_input, nullptr, nullptr, m, E);
    // 12-13. residual block a1
    gemm_fused<128, 128, EP_SILU><<<grid, 256>>>(
        m, ra1_W1, ra1_b1, nullptr, nullptr, nullptr, t1, E);
    gemm_fused<128, 128, EP_SILU_ADD><<<grid, 256>>>(
        t1, ra1_W2, ra1_b2, m, nullptr, nullptr, m, E);
    // 14-15. residual block a2 -> final output
    gemm_fused<128, 128, EP_SILU><<<grid, 256>>>(
        m, ra2_W1, ra2_b1, nullptr, nullptr, nullptr, t1, E);
    gemm_fused<128, 128, EP_SILU_ADD><<<grid, 256>>>(
        t1, ra2_W2, ra2_b2, m, nullptr, nullptr, outp, E);
}

// round 6
// speedup vs baseline: 1.4592x; 1.2708x over previous
#include <cuda_runtime.h>
#include <cuda_bf16.h>
#include <cstdint>

// ---------------- problem constants (fixed for this dataset) ----------------
#define D_    128
#define DA_   64
#define DB_   8
#define NR_   6
#define NS_   42
#define E_MAX 200000
#define T_MAX 1600000

// ---------------- scratch (static device globals; no allocation) ------------
__device__ __align__(16) float g_t1  [(size_t)E_MAX * D_];
__device__ __align__(16) float g_mbuf[(size_t)E_MAX * D_];
__device__ __align__(16) float g_down[(size_t)E_MAX * DA_];
__device__ __align__(16) float g_agg [(size_t)E_MAX * DA_];
__device__ __align__(16) float g_hrbf[(size_t)E_MAX * DB_];
__device__ __align__(16) float g_hsbf[(size_t)T_MAX * DB_];
// pre-split + fragment-permuted weights (bf16x2 packed in u32)
__device__ __align__(16) uint32_t g_whi[81920];
__device__ __align__(16) uint32_t g_wlo[81920];

// u32 offsets of each weight's fragment block
#define OFF_Wkj    0
#define OFF_Wji    8192
#define OFF_rb1W1  16384
#define OFF_rb1W2  24576
#define OFF_Wfin   32768
#define OFF_ra1W1  40960
#define OFF_ra1W2  49152
#define OFF_ra2W1  57344
#define OFF_ra2W2  65536
#define OFF_Wdown  73728
#define OFF_Wup    77824

// ---------------- helpers ----------------------------------------------------
__device__ __forceinline__ float silu_f(float x) {
    return x / (1.0f + __expf(-x));
}

// split x into bf16 hi + bf16 lo (x ~= hi + lo), pack two lanes into u32 pairs
__device__ __forceinline__ void splitpack2(float x0, float x1,
                                           uint32_t& hi, uint32_t& lo) {
    unsigned short h0 = __bfloat16_as_ushort(__float2bfloat16_rn(x0));
    unsigned short h1 = __bfloat16_as_ushort(__float2bfloat16_rn(x1));
    float f0 = __uint_as_float((uint32_t)h0 << 16);
    float f1 = __uint_as_float((uint32_t)h1 << 16);
    unsigned short l0 = __bfloat16_as_ushort(__float2bfloat16_rn(x0 - f0));
    unsigned short l1 = __bfloat16_as_ushort(__float2bfloat16_rn(x1 - f1));
    hi = (uint32_t)h0 | ((uint32_t)h1 << 16);
    lo = (uint32_t)l0 | ((uint32_t)l1 << 16);
}

__device__ __forceinline__ void mma_bf16(float* c, const uint32_t* a, const uint32_t* b) {
    asm volatile(
        "mma.sync.aligned.m16n8k16.row.col.f32.bf16.bf16.f32 "
        "{%0,%1,%2,%3}, {%4,%5,%6,%7}, {%8,%9}, {%0,%1,%2,%3};"
        : "+f"(c[0]), "+f"(c[1]), "+f"(c[2]), "+f"(c[3])
        : "r"(a[0]), "r"(a[1]), "r"(a[2]), "r"(a[3]), "r"(b[0]), "r"(b[1]));
}

// ---------------- epilogue modes ---------------------------------------------
#define EP_SILU        0
#define EP_SILU_ADD    1
#define EP_SILU_MULRBF 2

// ---------------- tensor-core GEMM: out = epi(A[E,KDIM] @ W[KDIM,NT]) ---------
// CTA tile 128 x NT, 8 warps in 2(M) x 4(N) grid, warp tile 64 x (NT/4).
// W pre-split/permuted into mma fragment layout (hi+lo, whole K resident in smem).
// A split to bf16 hi/lo during 16-K double-buffered staging.
// 3-term product: ah*wh + ah*wl + al*wh, fp32 accumulate.
template <int KDIM, int NT, int MODE>
__global__ void __launch_bounds__(256, 2) gemm_mma(
    const float* __restrict__ A,
    const uint32_t* __restrict__ whi, const uint32_t* __restrict__ wlo,
    const float* __restrict__ bias, const float* __restrict__ res,
    const float* __restrict__ hrbf, const float* __restrict__ wrbf2,
    float* __restrict__ out, int E)
{
    constexpr int NKS = KDIM / 16;        // k16 steps
    constexpr int NTN = NT / 8;           // n-tiles per CTA
    constexpr int NWN = NT / 32;          // n-tiles per warp (4 or 2)
    constexpr int SM_B = 4608;
    constexpr int BH_BYTES = 2 * KDIM * NT;       // bytes of hi frag region
    constexpr int SM_A = SM_B + 4 * KDIM * NT;    // A frag region (2 buf x hi/lo x 8 tiles x 512B)

    extern __shared__ char smem[];
    float* sBias = (float*)smem;
    float* sW2   = (float*)(smem + 512);

    const int tid  = threadIdx.x;
    const int lane = tid & 31;
    const int wid  = tid >> 5;
    const int warpM = wid >> 2;           // 0..1
    const int warpN = wid & 3;            // 0..3
    const int rowBase = blockIdx.x * 128;

    if (tid < NT) sBias[tid] = bias ? bias[tid] : 0.0f;
    if (MODE == EP_SILU_MULRBF)
        for (int i = tid; i < DB_ * NT; i += 256) sW2[i] = wrbf2[i];

    // ---- copy pre-permuted W fragments (hi & lo) into smem ----
    {
        constexpr int CNT4 = (KDIM * NT / 2) / 4;   // uint4 per array
        uint4* dh = (uint4*)(smem + SM_B);
        uint4* dl = (uint4*)(smem + SM_B + BH_BYTES);
        const uint4* shp = (const uint4*)whi;
        const uint4* slp = (const uint4*)wlo;
        for (int i = tid; i < CNT4; i += 256) {
            dh[i] = __ldg(shp + i);
            dl[i] = __ldg(slp + i);
        }
    }

    // ---- A staging: load 4 fragment positions (float2 each) ----
    auto stageLoad = [&](int s, float2* pv) {
        const int k0 = s * 16;
#pragma unroll
        for (int p = 0; p < 4; p++) {
            int tr = (tid >> 5) + p * 8;
            int mt = tr >> 2, reg = tr & 3;
            int row = rowBase + mt * 16 + (lane >> 2) + ((reg & 1) << 3);
            int kc  = k0 + 2 * (lane & 3) + ((reg & 2) << 2);
            pv[p] = (row < E) ? *(const float2*)(A + (size_t)row * KDIM + kc)
                              : make_float2(0.f, 0.f);
        }
    };
    auto stageStore = [&](int buf, const float2* pv) {
#pragma unroll
        for (int p = 0; p < 4; p++) {
            int tr = (tid >> 5) + p * 8;
            int mt = tr >> 2, reg = tr & 3;
            uint32_t hi, lo;
            splitpack2(pv[p].x, pv[p].y, hi, lo);
            int offh = SM_A + ((buf * 2 + 0) * 8 + mt) * 512 + reg * 128 + (lane << 2);
            int offl = SM_A + ((buf * 2 + 1) * 8 + mt) * 512 + reg * 128 + (lane << 2);
            *(uint32_t*)(smem + offh) = hi;
            *(uint32_t*)(smem + offl) = lo;
        }
    };

    float acc[4][NWN][4];
#pragma unroll
    for (int mt = 0; mt < 4; mt++)
#pragma unroll
        for (int nt = 0; nt < NWN; nt++)
#pragma unroll
            for (int j = 0; j < 4; j++) acc[mt][nt][j] = 0.f;

    {
        float2 pv[4];
        stageLoad(0, pv);
        stageStore(0, pv);
    }
    __syncthreads();

    for (int s = 0; s < NKS; s++) {
        const int buf = s & 1;
        float2 pv[4];
        if (s + 1 < NKS) stageLoad(s + 1, pv);

        uint32_t ahi[4][4], alo[4][4];
#pragma unroll
        for (int mt = 0; mt < 4; mt++) {
            int gm = warpM * 4 + mt;
            int bh = SM_A + ((buf * 2 + 0) * 8 + gm) * 512 + (lane << 2);
            int bl = SM_A + ((buf * 2 + 1) * 8 + gm) * 512 + (lane << 2);
#pragma unroll
            for (int r = 0; r < 4; r++) {
                ahi[mt][r] = *(const uint32_t*)(smem + bh + r * 128);
                alo[mt][r] = *(const uint32_t*)(smem + bl + r * 128);
            }
        }
#pragma unroll
        for (int nt = 0; nt < NWN; nt++) {
            int gt = warpN * NWN + nt;
            const char* bp = smem + SM_B + ((((s * NTN) + gt) * 32 + lane) << 3);
            uint2 bh = *(const uint2*)bp;
            uint2 bl = *(const uint2*)(bp + BH_BYTES);
            uint32_t bhv[2] = {bh.x, bh.y};
            uint32_t blv[2] = {bl.x, bl.y};
#pragma unroll
            for (int mt = 0; mt < 4; mt++) {
                mma_bf16(acc[mt][nt], ahi[mt], bhv);
                mma_bf16(acc[mt][nt], ahi[mt], blv);
                mma_bf16(acc[mt][nt], alo[mt], bhv);
            }
        }
        if (s + 1 < NKS) stageStore(buf ^ 1, pv);
        __syncthreads();
    }

    // ---- epilogue ----
#pragma unroll
    for (int mt = 0; mt < 4; mt++) {
#pragma unroll
        for (int half = 0; half < 2; half++) {
            int row = rowBase + warpM * 64 + mt * 16 + (lane >> 2) + half * 8;
            if (row >= E) continue;
            float hh[8];
            if (MODE == EP_SILU_MULRBF) {
                float4 h0 = __ldg((const float4*)(hrbf + (size_t)row * DB_));
                float4 h1 = __ldg((const float4*)(hrbf + (size_t)row * DB_ + 4));
                hh[0] = h0.x; hh[1] = h0.y; hh[2] = h0.z; hh[3] = h0.w;
                hh[4] = h1.x; hh[5] = h1.y; hh[6] = h1.z; hh[7] = h1.w;
            }
#pragma unroll
            for (int nt = 0; nt < NWN; nt++) {
                int col = warpN * NWN * 8 + nt * 8 + 2 * (lane & 3);
                float v0 = acc[mt][nt][half * 2 + 0] + sBias[col];
                float v1 = acc[mt][nt][half * 2 + 1] + sBias[col + 1];
                float s0 = silu_f(v0), s1 = silu_f(v1);
                if (MODE == EP_SILU_ADD) {
                    float2 rr = __ldg((const float2*)(res + (size_t)row * NT + col));
                    s0 += rr.x; s1 += rr.y;
                } else if (MODE == EP_SILU_MULRBF) {
                    float r0 = 0.f, r1 = 0.f;
#pragma unroll
                    for (int j = 0; j < DB_; j++) {
                        r0 += hh[j] * sW2[j * NT + col];
                        r1 += hh[j] * sW2[j * NT + col + 1];
                    }
                    s0 *= r0; s1 *= r1;
                }
                *(float2*)(out + (size_t)row * NT + col) = make_float2(s0, s1);
            }
        }
    }
}

// ---------------- weight fragment prep: split + permute -----------------------
// Output layout (u32 index): ((s*(N/8) + t)*32 + lane)*2 + reg
//   reg0: {W[k0][n], W[k0+1][n]},  reg1: {W[k0+8][n], W[k0+9][n]}
//   k0 = s*16 + 2*(lane%4), n = t*8 + lane/4
__global__ void __launch_bounds__(256) k_wfrag(
    const float* __restrict__ W, int K, int N,
    uint32_t* __restrict__ hi, uint32_t* __restrict__ lo)
{
    int idx = blockIdx.x * 256 + threadIdx.x;
    int total = (K / 16) * (N / 8) * 64;
    if (idx >= total) return;
    int reg  = idx & 1;
    int lane = (idx >> 1) & 31;
    int st   = idx >> 6;
    int t    = st % (N / 8);
    int s    = st / (N / 8);
    int q = lane & 3, r = lane >> 2;
    int k0 = s * 16 + 2 * q + (reg ? 8 : 0);
    int n  = t * 8 + r;
    float w0 = __ldg(W + (size_t)k0 * N + n);
    float w1 = __ldg(W + (size_t)(k0 + 1) * N + n);
    uint32_t h, l;
    splitpack2(w0, w1, h, l);
    hi[idx] = h;
    lo[idx] = l;
}

// ---------------- small kernels (unchanged, validated) ------------------------
__global__ void __launch_bounds__(256) k_zero(float4* __restrict__ p, int n4) {
    int i = blockIdx.x * blockDim.x + threadIdx.x;
    if (i < n4) p[i] = make_float4(0.f, 0.f, 0.f, 0.f);
}

__global__ void __launch_bounds__(256) k_hrbf(
    const float* __restrict__ rbf, const float* __restrict__ w1,
    float* __restrict__ out, int E)
{
    __shared__ float sw[NR_ * DB_];
    if (threadIdx.x < NR_ * DB_) sw[threadIdx.x] = w1[threadIdx.x];
    __syncthreads();
    int r = blockIdx.x * blockDim.x + threadIdx.x;
    if (r >= E) return;
    float x[NR_];
#pragma unroll
    for (int j = 0; j < NR_; j++) x[j] = __ldg(rbf + (size_t)r * NR_ + j);
    float h[DB_];
#pragma unroll
    for (int k = 0; k < DB_; k++) h[k] = 0.f;
#pragma unroll
    for (int j = 0; j < NR_; j++)
#pragma unroll
        for (int k = 0; k < DB_; k++) h[k] += x[j] * sw[j * DB_ + k];
    float4* op = (float4*)(out + (size_t)r * DB_);
    op[0] = make_float4(h[0], h[1], h[2], h[3]);
    op[1] = make_float4(h[4], h[5], h[6], h[7]);
}

__global__ void __launch_bounds__(256) k_hsbf(
    const float* __restrict__ sbf, const float* __restrict__ w1,
    float* __restrict__ out, int T)
{
    __shared__ float st[256 * NS_];
    __shared__ float sw[NS_ * DB_];
    for (int i = threadIdx.x; i < NS_ * DB_; i += 256) sw[i] = w1[i];

    int base = blockIdx.x * 256;
    int n = T - base; if (n > 256) n = 256;
    int total = n * NS_;
    for (int i = threadIdx.x; i < total; i += 256)
        st[i] = sbf[(size_t)base * NS_ + i];
    __syncthreads();

    int r = threadIdx.x;
    if (r >= n) return;
    const float* x = &st[r * NS_];
    float h[DB_];
#pragma unroll
    for (int k = 0; k < DB_; k++) h[k] = 0.f;
#pragma unroll
    for (int j = 0; j < NS_; j++) {
        float xv = x[j];
#pragma unroll
        for (int k = 0; k < DB_; k++) h[k] += xv * sw[j * DB_ + k];
    }
    float4* op = (float4*)(out + (size_t)(base + r) * DB_);
    op[0] = make_float4(h[0], h[1], h[2], h[3]);
    op[1] = make_float4(h[4], h[5], h[6], h[7]);
}

__global__ void __launch_bounds__(256) k_triplet(
    const float* __restrict__ hsbf, const float* __restrict__ wsbf2,
    const int* __restrict__ exp_kj, const int* __restrict__ red_ji,
    const float* __restrict__ down, float* __restrict__ agg, int T)
{
    __shared__ float sw[DB_ * DA_];
    for (int i = threadIdx.x; i < DB_ * DA_; i += 256) sw[i] = wsbf2[i];
    __syncthreads();

    const int q = threadIdx.x & 15;
    float w[DB_][4];
#pragma unroll
    for (int i = 0; i < DB_; i++)
#pragma unroll
        for (int j = 0; j < 4; j++) w[i][j] = sw[i * DA_ + q * 4 + j];

    int t = (blockIdx.x * blockDim.x + threadIdx.x) >> 4;
    const int stride = (gridDim.x * blockDim.x) >> 4;

    for (; t < T; t += stride) {
        int e = __ldg(exp_kj + t);
        int g = __ldg(red_ji + t);
        const float4* hp = (const float4*)(hsbf + (size_t)t * DB_);
        float4 h0 = __ldg(hp), h1 = __ldg(hp + 1);
        float hh[8] = {h0.x, h0.y, h0.z, h0.w, h1.x, h1.y, h1.z, h1.w};

        float s0 = 0.f, s1 = 0.f, s2 = 0.f, s3 = 0.f;
#pragma unroll
        for (int i = 0; i < DB_; i++) {
            s0 += hh[i] * w[i][0];
            s1 += hh[i] * w[i][1];
            s2 += hh[i] * w[i][2];
            s3 += hh[i] * w[i][3];
        }
        float4 a = __ldg((const float4*)(down + (size_t)e * DA_ + q * 4));
        float vx = a.x * s0, vy = a.y * s1, vz = a.z * s2, vw = a.w * s3;

        float* dst = agg + (size_t)g * DA_ + q * 4;
        asm volatile("red.global.add.v4.f32 [%0], {%1, %2, %3, %4};"
                     :: "l"(dst), "f"(vx), "f"(vy), "f"(vz), "f"(vw)
                     : "memory");
    }
}

// ---------------- launch -------------------------------------------------------
static inline int smem_sz(int K, int N) { return 4608 + 4 * K * N + 16384; }

extern "C" void kernel_launch(void* const* d_in, const int* in_sizes, int n_in,
                              void* d_out, int out_size)
{
    const float* m_input  = (const float*)d_in[0];
    const float* rbf      = (const float*)d_in[1];
    const float* sbf      = (const float*)d_in[2];
    const float* Wkj      = (const float*)d_in[3];
    const float* bkj      = (const float*)d_in[4];
    const float* Wrbf1    = (const float*)d_in[5];
    const float* Wrbf2    = (const float*)d_in[6];
    const float* Wdown    = (const float*)d_in[7];
    const float* Wsbf1    = (const float*)d_in[8];
    const float* Wsbf2    = (const float*)d_in[9];
    const float* Wup      = (const float*)d_in[10];
    const float* Wji      = (const float*)d_in[11];
    const float* bji      = (const float*)d_in[12];
    const float* rb1_W1   = (const float*)d_in[13];
    const float* rb1_b1   = (const float*)d_in[14];
    const float* rb1_W2   = (const float*)d_in[15];
    const float* rb1_b2   = (const float*)d_in[16];
    const float* Wfin     = (const float*)d_in[17];
    const float* bfin     = (const float*)d_in[18];
    const float* ra1_W1   = (const float*)d_in[19];
    const float* ra1_b1   = (const float*)d_in[20];
    const float* ra1_W2   = (const float*)d_in[21];
    const float* ra1_b2   = (const float*)d_in[22];
    const float* ra2_W1   = (const float*)d_in[23];
    const float* ra2_b1   = (const float*)d_in[24];
    const float* ra2_W2   = (const float*)d_in[25];
    const float* ra2_b2   = (const float*)d_in[26];
    const int*   red_ji   = (const int*)  d_in[27];
    const int*   exp_kj   = (const int*)  d_in[28];

    const int E = in_sizes[0] / D_;
    const int T = in_sizes[27];

    float *t1, *m, *down, *agg, *hrbf, *hsbf;
    uint32_t *whi, *wlo;
    cudaGetSymbolAddress((void**)&t1,   g_t1);
    cudaGetSymbolAddress((void**)&m,    g_mbuf);
    cudaGetSymbolAddress((void**)&down, g_down);
    cudaGetSymbolAddress((void**)&agg,  g_agg);
    cudaGetSymbolAddress((void**)&hrbf, g_hrbf);
    cudaGetSymbolAddress((void**)&hsbf, g_hsbf);
    cudaGetSymbolAddress((void**)&whi,  g_whi);
    cudaGetSymbolAddress((void**)&wlo,  g_wlo);

    float* outp = (float*)d_out;
    const int grid = (E + 127) / 128;

    const int S_FF = smem_sz(128, 128);   // 86528
    const int S_FD = smem_sz(128, 64);    // 53760
    const int S_DF = smem_sz(64, 128);    // 53760
    cudaFuncSetAttribute((const void*)gemm_mma<128,128,EP_SILU>,        cudaFuncAttributeMaxDynamicSharedMemorySize, S_FF);
    cudaFuncSetAttribute((const void*)gemm_mma<128,128,EP_SILU_ADD>,    cudaFuncAttributeMaxDynamicSharedMemorySize, S_FF);
    cudaFuncSetAttribute((const void*)gemm_mma<128,128,EP_SILU_MULRBF>, cudaFuncAttributeMaxDynamicSharedMemorySize, S_FF);
    cudaFuncSetAttribute((const void*)gemm_mma<128,64, EP_SILU>,        cudaFuncAttributeMaxDynamicSharedMemorySize, S_FD);
    cudaFuncSetAttribute((const void*)gemm_mma<64,128, EP_SILU>,        cudaFuncAttributeMaxDynamicSharedMemorySize, S_DF);

    // ---- weight fragment prep (split + permute) ----
    k_wfrag<<<32, 256>>>(Wkj,    128, 128, whi + OFF_Wkj,   wlo + OFF_Wkj);
    k_wfrag<<<32, 256>>>(Wji,    128, 128, whi + OFF_Wji,   wlo + OFF_Wji);
    k_wfrag<<<32, 256>>>(rb1_W1, 128, 128, whi + OFF_rb1W1, wlo + OFF_rb1W1);
    k_wfrag<<<32, 256>>>(rb1_W2, 128, 128, whi + OFF_rb1W2, wlo + OFF_rb1W2);
    k_wfrag<<<32, 256>>>(Wfin,   128, 128, whi + OFF_Wfin,  wlo + OFF_Wfin);
    k_wfrag<<<32, 256>>>(ra1_W1, 128, 128, whi + OFF_ra1W1, wlo + OFF_ra1W1);
    k_wfrag<<<32, 256>>>(ra1_W2, 128, 128, whi + OFF_ra1W2, wlo + OFF_ra1W2);
    k_wfrag<<<32, 256>>>(ra2_W1, 128, 128, whi + OFF_ra2W1, wlo + OFF_ra2W1);
    k_wfrag<<<32, 256>>>(ra2_W2, 128, 128, whi + OFF_ra2W2, wlo + OFF_ra2W2);
    k_wfrag<<<16, 256>>>(Wdown,  128, 64,  whi + OFF_Wdown, wlo + OFF_Wdown);
    k_wfrag<<<16, 256>>>(Wup,    64,  128, whi + OFF_Wup,   wlo + OFF_Wup);

    // 1. zero aggregation buffer
    {
        int n4 = (E * DA_) / 4;
        k_zero<<<(n4 + 255) / 256, 256>>>((float4*)agg, n4);
    }
    // 2-3. small basis projections
    k_hrbf<<<(E + 255) / 256, 256>>>(rbf, Wrbf1, hrbf, E);
    k_hsbf<<<(T + 255) / 256, 256>>>(sbf, Wsbf1, hsbf, T);

    // 4. m_ang = silu(m_input @ Wkj + bkj) * (h_rbf @ Wrbf2)   -> t1 [E,128]
    gemm_mma<128,128,EP_SILU_MULRBF><<<grid, 256, S_FF>>>(
        m_input, whi + OFF_Wkj, wlo + OFF_Wkj, bkj, nullptr, hrbf, Wrbf2, t1, E);
    // 5. down = silu(t1 @ Wdown)                               -> down [E,64]
    gemm_mma<128,64,EP_SILU><<<grid, 256, S_FD>>>(
        t1, whi + OFF_Wdown, wlo + OFF_Wdown, nullptr, nullptr, nullptr, nullptr, down, E);
    // 6. triplet gather / sbf-mod / scatter-add                -> agg [E,64]
    k_triplet<<<2048, 256>>>(hsbf, Wsbf2, exp_kj, red_ji, down, agg, T);
    // 7. prop = silu(agg @ Wup)                                -> t1 [E,128]
    gemm_mma<64,128,EP_SILU><<<grid, 256, S_DF>>>(
        agg, whi + OFF_Wup, wlo + OFF_Wup, nullptr, nullptr, nullptr, nullptr, t1, E);
    // 8. m = silu(m_input @ Wji + bji) + prop
    gemm_mma<128,128,EP_SILU_ADD><<<grid, 256, S_FF>>>(
        m_input, whi + OFF_Wji, wlo + OFF_Wji, bji, t1, nullptr, nullptr, m, E);
    // 9-10. residual block b1
    gemm_mma<128,128,EP_SILU><<<grid, 256, S_FF>>>(
        m, whi + OFF_rb1W1, wlo + OFF_rb1W1, rb1_b1, nullptr, nullptr, nullptr, t1, E);
    gemm_mma<128,128,EP_SILU_ADD><<<grid, 256, S_FF>>>(
        t1, whi + OFF_rb1W2, wlo + OFF_rb1W2, rb1_b2, m, nullptr, nullptr, m, E);
    // 11. m = silu(m @ Wfin + bfin) + m_input
    gemm_mma<128,128,EP_SILU_ADD><<<grid, 256, S_FF>>>(
        m, whi + OFF_Wfin, wlo + OFF_Wfin, bfin, m_input, nullptr, nullptr, m, E);
    // 12-13. residual block a1
    gemm_mma<128,128,EP_SILU><<<grid, 256, S_FF>>>(
        m, whi + OFF_ra1W1, wlo + OFF_ra1W1, ra1_b1, nullptr, nullptr, nullptr, t1, E);
    gemm_mma<128,128,EP_SILU_ADD><<<grid, 256, S_FF>>>(
        t1, whi + OFF_ra1W2, wlo + OFF_ra1W2, ra1_b2, m, nullptr, nullptr, m, E);
    // 14-15. residual block a2 -> final output
    gemm_mma<128,128,EP_SILU><<<grid, 256, S_FF>>>(
        m, whi + OFF_ra2W1, wlo + OFF_ra2W1, ra2_b1, nullptr, nullptr, nullptr, t1, E);
    gemm_mma<128,128,EP_SILU_ADD><<<grid, 256, S_FF>>>(
        t1, whi + OFF_ra2W2, wlo + OFF_ra2W2, ra2_b2, m, nullptr, nullptr, outp, E);
}

// round 7
// speedup vs baseline: 1.6076x; 1.1018x over previous
#include <cuda_runtime.h>
#include <cuda_bf16.h>
#include <cstdint>

// ---------------- problem constants (fixed for this dataset) ----------------
#define D_    128
#define DA_   64
#define DB_   8
#define NR_   6
#define NS_   42
#define E_MAX 200000
#define T_MAX 1600000

// ---------------- scratch (static device globals; no allocation) ------------
__device__ __align__(16) float g_t1  [(size_t)E_MAX * D_];
__device__ __align__(16) float g_mbuf[(size_t)E_MAX * D_];
__device__ __align__(16) float g_down[(size_t)E_MAX * DA_];
__device__ __align__(16) float g_agg [(size_t)E_MAX * DA_];
__device__ __align__(16) float g_hrbf[(size_t)E_MAX * DB_];
__device__ __align__(16) float g_hsbf[(size_t)T_MAX * DB_];
// prepacked weight fragments, hi/lo interleaved per uint4: {bh0,bh1,bl0,bl1}
__device__ __align__(16) uint32_t g_wfrag[163840];

// u32 offsets of each weight's fragment block
#define OFF_Wkj    0
#define OFF_Wji    16384
#define OFF_rb1W1  32768
#define OFF_rb1W2  49152
#define OFF_Wfin   65536
#define OFF_ra1W1  81920
#define OFF_ra1W2  98304
#define OFF_ra2W1  114688
#define OFF_ra2W2  131072
#define OFF_Wdown  147456
#define OFF_Wup    155648

// ---------------- helpers ----------------------------------------------------
__device__ __forceinline__ float silu_f(float x) {
    return x / (1.0f + __expf(-x));
}

// packed split: (x0,x1) -> bf16x2 hi (lower=x0) and bf16x2 lo residuals
__device__ __forceinline__ void splitpack2(float x0, float x1,
                                           uint32_t& hi, uint32_t& lo) {
    asm("cvt.rn.bf16x2.f32 %0, %1, %2;" : "=r"(hi) : "f"(x1), "f"(x0));
    float f0 = __uint_as_float(hi << 16);
    float f1 = __uint_as_float(hi & 0xFFFF0000u);
    float l0 = x0 - f0;
    float l1 = x1 - f1;
    asm("cvt.rn.bf16x2.f32 %0, %1, %2;" : "=r"(lo) : "f"(l1), "f"(l0));
}

__device__ __forceinline__ void mma_bf16(float* c, const uint32_t* a, const uint32_t* b) {
    asm volatile(
        "mma.sync.aligned.m16n8k16.row.col.f32.bf16.bf16.f32 "
        "{%0,%1,%2,%3}, {%4,%5,%6,%7}, {%8,%9}, {%0,%1,%2,%3};"
        : "+f"(c[0]), "+f"(c[1]), "+f"(c[2]), "+f"(c[3])
        : "r"(a[0]), "r"(a[1]), "r"(a[2]), "r"(a[3]), "r"(b[0]), "r"(b[1]));
}

__device__ __forceinline__ void cp_async16(uint32_t saddr, const void* gaddr) {
    asm volatile("cp.async.cg.shared.global [%0], [%1], 16;"
                 :: "r"(saddr), "l"(gaddr));
}
__device__ __forceinline__ uint32_t smem_u32(const void* p) {
    uint32_t a;
    asm("{ .reg .u64 t; cvta.to.shared.u64 t, %1; cvt.u32.u64 %0, t; }" : "=r"(a) : "l"(p));
    return a;
}

// ---------------- epilogue modes ---------------------------------------------
#define EP_SILU        0
#define EP_SILU_ADD    1
#define EP_SILU_MULRBF 2

// ---------------- tensor-core GEMM: out = epi(A[E,KDIM] @ W[KDIM,NT]) ---------
// CTA tile 128 x NT, 8 warps (2M x 4N), warp tile 64 x (NT/4).
// W pre-split/permuted fragments (hi/lo interleaved) resident in smem.
// A split to bf16 hi/lo during k16 double-buffered staging; fragment layout is
// register-contiguous so consume is LDS.128 and staging store is STS.128.
// 3-term product: ah*wh + ah*wl + al*wh, fp32 accumulate.
template <int KDIM, int NT, int MODE>
__global__ void __launch_bounds__(256, 2) gemm_mma(
    const float* __restrict__ A,
    const uint32_t* __restrict__ wfrag,
    const float* __restrict__ bias, const float* __restrict__ res,
    const float* __restrict__ hrbf, const float* __restrict__ wrbf2,
    float* __restrict__ out, int E)
{
    constexpr int NKS = KDIM / 16;            // k16 steps
    constexpr int NTN = NT / 8;               // n-tiles per CTA
    constexpr int NWN = NT / 32;              // n-tiles per warp (4 or 2)
    constexpr int SM_B = 4608;
    constexpr int B_BYTES = KDIM * NT * 4;    // interleaved hi/lo fragment bytes
    constexpr int SM_A = SM_B + B_BYTES;      // A frag region: 2buf x 2(hi/lo) x 8mt x 32lane x 16B

    extern __shared__ char smem[];
    const uint32_t sb = smem_u32(smem);
    float* sBias = (float*)smem;
    float* sW2   = (float*)(smem + 512);

    const int tid  = threadIdx.x;
    const int lane = tid & 31;
    const int wid  = tid >> 5;
    const int warpM = wid >> 2;               // 0..1
    const int warpN = wid & 3;                // 0..3
    const int rowBase = blockIdx.x * 128;

    // ---- async copy of prepacked W fragments into smem ----
    {
        constexpr int CNT4 = B_BYTES / 16;
        const uint4* src = (const uint4*)wfrag;
#pragma unroll
        for (int i = 0; i < CNT4 / 256; i++) {
            int f = tid + i * 256;
            cp_async16(sb + SM_B + f * 16, src + f);
        }
        asm volatile("cp.async.commit_group;" ::: "memory");
    }

    if (tid < NT) sBias[tid] = bias ? bias[tid] : 0.0f;
    if (MODE == EP_SILU_MULRBF)
        for (int i = tid; i < DB_ * NT; i += 256) sW2[i] = wrbf2[i];

    // ---- A staging: thread owns (mt = tid>>5, lane); loads its 4 mma regs ----
    const int smt   = tid >> 5;
    const int row0  = rowBase + smt * 16 + (lane >> 2);
    const int kcOff = 2 * (lane & 3);

    auto stageLoad = [&](int s, float2* pv) {
        const int kc0 = s * 16 + kcOff;
        const float* base0 = A + (size_t)row0 * KDIM + kc0;
        const float* base1 = base0 + (size_t)8 * KDIM;
        bool ok0 = (row0 < E), ok1 = (row0 + 8 < E);
        pv[0] = ok0 ? *(const float2*)(base0)     : make_float2(0.f, 0.f);
        pv[1] = ok1 ? *(const float2*)(base1)     : make_float2(0.f, 0.f);
        pv[2] = ok0 ? *(const float2*)(base0 + 8) : make_float2(0.f, 0.f);
        pv[3] = ok1 ? *(const float2*)(base1 + 8) : make_float2(0.f, 0.f);
    };
    auto stageStore = [&](int buf, const float2* pv) {
        uint32_t hi[4], lo[4];
#pragma unroll
        for (int p = 0; p < 4; p++) splitpack2(pv[p].x, pv[p].y, hi[p], lo[p]);
        int offh = SM_A + (((buf * 2 + 0) * 8 + smt) * 32 + lane) * 16;
        int offl = SM_A + (((buf * 2 + 1) * 8 + smt) * 32 + lane) * 16;
        *(uint4*)(smem + offh) = make_uint4(hi[0], hi[1], hi[2], hi[3]);
        *(uint4*)(smem + offl) = make_uint4(lo[0], lo[1], lo[2], lo[3]);
    };

    float acc[4][NWN][4];
#pragma unroll
    for (int mt = 0; mt < 4; mt++)
#pragma unroll
        for (int nt = 0; nt < NWN; nt++)
#pragma unroll
            for (int j = 0; j < 4; j++) acc[mt][nt][j] = 0.f;

    {
        float2 pv[4];
        stageLoad(0, pv);
        stageStore(0, pv);
    }
    asm volatile("cp.async.wait_group 0;" ::: "memory");
    __syncthreads();

    for (int s = 0; s < NKS; s++) {
        const int buf = s & 1;
        float2 pv[4];
        if (s + 1 < NKS) stageLoad(s + 1, pv);

        // A fragments: one LDS.128 per (mt, hi/lo)
        uint4 ahi[4], alo[4];
#pragma unroll
        for (int mt = 0; mt < 4; mt++) {
            int gm = warpM * 4 + mt;
            ahi[mt] = *(const uint4*)(smem + SM_A + (((buf * 2 + 0) * 8 + gm) * 32 + lane) * 16);
            alo[mt] = *(const uint4*)(smem + SM_A + (((buf * 2 + 1) * 8 + gm) * 32 + lane) * 16);
        }
#pragma unroll
        for (int nt = 0; nt < NWN; nt++) {
            int gt = warpN * NWN + nt;
            uint4 bq = *(const uint4*)(smem + SM_B + (((s * NTN) + gt) * 32 + lane) * 16);
            uint32_t bh[2] = {bq.x, bq.y};
            uint32_t bl[2] = {bq.z, bq.w};
#pragma unroll
            for (int mt = 0; mt < 4; mt++) {
                mma_bf16(acc[mt][nt], (const uint32_t*)&ahi[mt], bh);
                mma_bf16(acc[mt][nt], (const uint32_t*)&ahi[mt], bl);
                mma_bf16(acc[mt][nt], (const uint32_t*)&alo[mt], bh);
            }
        }
        if (s + 1 < NKS) stageStore(buf ^ 1, pv);
        __syncthreads();
    }

    // ---- epilogue ----
#pragma unroll
    for (int mt = 0; mt < 4; mt++) {
#pragma unroll
        for (int half = 0; half < 2; half++) {
            int row = rowBase + warpM * 64 + mt * 16 + (lane >> 2) + half * 8;
            if (row >= E) continue;
            float hh[8];
            if (MODE == EP_SILU_MULRBF) {
                float4 h0 = __ldg((const float4*)(hrbf + (size_t)row * DB_));
                float4 h1 = __ldg((const float4*)(hrbf + (size_t)row * DB_ + 4));
                hh[0] = h0.x; hh[1] = h0.y; hh[2] = h0.z; hh[3] = h0.w;
                hh[4] = h1.x; hh[5] = h1.y; hh[6] = h1.z; hh[7] = h1.w;
            }
#pragma unroll
            for (int nt = 0; nt < NWN; nt++) {
                int col = warpN * NWN * 8 + nt * 8 + 2 * (lane & 3);
                float v0 = acc[mt][nt][half * 2 + 0] + sBias[col];
                float v1 = acc[mt][nt][half * 2 + 1] + sBias[col + 1];
                float s0 = silu_f(v0), s1 = silu_f(v1);
                if (MODE == EP_SILU_ADD) {
                    float2 rr = __ldg((const float2*)(res + (size_t)row * NT + col));
                    s0 += rr.x; s1 += rr.y;
                } else if (MODE == EP_SILU_MULRBF) {
                    float r0 = 0.f, r1 = 0.f;
#pragma unroll
                    for (int j = 0; j < DB_; j++) {
                        r0 += hh[j] * sW2[j * NT + col];
                        r1 += hh[j] * sW2[j * NT + col + 1];
                    }
                    s0 *= r0; s1 *= r1;
                }
                *(float2*)(out + (size_t)row * NT + col) = make_float2(s0, s1);
            }
        }
    }
}

// ---------------- weight fragment prep: split + permute + interleave ----------
// Output (uint4 index): (s*(N/8) + t)*32 + lane  ->  {bh0, bh1, bl0, bl1}
//   bh0/bl0: {W[k0][n], W[k0+1][n]},  bh1/bl1: {W[k0+8][n], W[k0+9][n]}
//   k0 = s*16 + 2*(lane%4), n = t*8 + lane/4
__global__ void __launch_bounds__(256) k_wfrag(
    const float* __restrict__ W, int K, int N, uint32_t* __restrict__ outv)
{
    int idx = blockIdx.x * 256 + threadIdx.x;     // uint4 index
    int total = (K / 16) * (N / 8) * 32;
    if (idx >= total) return;
    int lane = idx & 31;
    int st   = idx >> 5;
    int t    = st % (N / 8);
    int s    = st / (N / 8);
    int q = lane & 3, r = lane >> 2;
    int n  = t * 8 + r;
    int k0 = s * 16 + 2 * q;

    float w00 = __ldg(W + (size_t)k0 * N + n);
    float w01 = __ldg(W + (size_t)(k0 + 1) * N + n);
    float w10 = __ldg(W + (size_t)(k0 + 8) * N + n);
    float w11 = __ldg(W + (size_t)(k0 + 9) * N + n);
    uint32_t h0, l0, h1, l1;
    splitpack2(w00, w01, h0, l0);
    splitpack2(w10, w11, h1, l1);
    ((uint4*)outv)[idx] = make_uint4(h0, h1, l0, l1);
}

// ---------------- small kernels (unchanged, validated) ------------------------
__global__ void __launch_bounds__(256) k_zero(float4* __restrict__ p, int n4) {
    int i = blockIdx.x * blockDim.x + threadIdx.x;
    if (i < n4) p[i] = make_float4(0.f, 0.f, 0.f, 0.f);
}

__global__ void __launch_bounds__(256) k_hrbf(
    const float* __restrict__ rbf, const float* __restrict__ w1,
    float* __restrict__ out, int E)
{
    __shared__ float sw[NR_ * DB_];
    if (threadIdx.x < NR_ * DB_) sw[threadIdx.x] = w1[threadIdx.x];
    __syncthreads();
    int r = blockIdx.x * blockDim.x + threadIdx.x;
    if (r >= E) return;
    float x[NR_];
#pragma unroll
    for (int j = 0; j < NR_; j++) x[j] = __ldg(rbf + (size_t)r * NR_ + j);
    float h[DB_];
#pragma unroll
    for (int k = 0; k < DB_; k++) h[k] = 0.f;
#pragma unroll
    for (int j = 0; j < NR_; j++)
#pragma unroll
        for (int k = 0; k < DB_; k++) h[k] += x[j] * sw[j * DB_ + k];
    float4* op = (float4*)(out + (size_t)r * DB_);
    op[0] = make_float4(h[0], h[1], h[2], h[3]);
    op[1] = make_float4(h[4], h[5], h[6], h[7]);
}

__global__ void __launch_bounds__(256) k_hsbf(
    const float* __restrict__ sbf, const float* __restrict__ w1,
    float* __restrict__ out, int T)
{
    __shared__ float st[256 * NS_];
    __shared__ float sw[NS_ * DB_];
    for (int i = threadIdx.x; i < NS_ * DB_; i += 256) sw[i] = w1[i];

    int base = blockIdx.x * 256;
    int n = T - base; if (n > 256) n = 256;
    int total = n * NS_;
    for (int i = threadIdx.x; i < total; i += 256)
        st[i] = sbf[(size_t)base * NS_ + i];
    __syncthreads();

    int r = threadIdx.x;
    if (r >= n) return;
    const float* x = &st[r * NS_];
    float h[DB_];
#pragma unroll
    for (int k = 0; k < DB_; k++) h[k] = 0.f;
#pragma unroll
    for (int j = 0; j < NS_; j++) {
        float xv = x[j];
#pragma unroll
        for (int k = 0; k < DB_; k++) h[k] += xv * sw[j * DB_ + k];
    }
    float4* op = (float4*)(out + (size_t)(base + r) * DB_);
    op[0] = make_float4(h[0], h[1], h[2], h[3]);
    op[1] = make_float4(h[4], h[5], h[6], h[7]);
}

__global__ void __launch_bounds__(256) k_triplet(
    const float* __restrict__ hsbf, const float* __restrict__ wsbf2,
    const int* __restrict__ exp_kj, const int* __restrict__ red_ji,
    const float* __restrict__ down, float* __restrict__ agg, int T)
{
    __shared__ float sw[DB_ * DA_];
    for (int i = threadIdx.x; i < DB_ * DA_; i += 256) sw[i] = wsbf2[i];
    __syncthreads();

    const int q = threadIdx.x & 15;
    float w[DB_][4];
#pragma unroll
    for (int i = 0; i < DB_; i++)
#pragma unroll
        for (int j = 0; j < 4; j++) w[i][j] = sw[i * DA_ + q * 4 + j];

    int t = (blockIdx.x * blockDim.x + threadIdx.x) >> 4;
    const int stride = (gridDim.x * blockDim.x) >> 4;

    for (; t < T; t += stride) {
        int e = __ldg(exp_kj + t);
        int g = __ldg(red_ji + t);
        const float4* hp = (const float4*)(hsbf + (size_t)t * DB_);
        float4 h0 = __ldg(hp), h1 = __ldg(hp + 1);
        float hh[8] = {h0.x, h0.y, h0.z, h0.w, h1.x, h1.y, h1.z, h1.w};

        float s0 = 0.f, s1 = 0.f, s2 = 0.f, s3 = 0.f;
#pragma unroll
        for (int i = 0; i < DB_; i++) {
            s0 += hh[i] * w[i][0];
            s1 += hh[i] * w[i][1];
            s2 += hh[i] * w[i][2];
            s3 += hh[i] * w[i][3];
        }
        float4 a = __ldg((const float4*)(down + (size_t)e * DA_ + q * 4));
        float vx = a.x * s0, vy = a.y * s1, vz = a.z * s2, vw = a.w * s3;

        float* dst = agg + (size_t)g * DA_ + q * 4;
        asm volatile("red.global.add.v4.f32 [%0], {%1, %2, %3, %4};"
                     :: "l"(dst), "f"(vx), "f"(vy), "f"(vz), "f"(vw)
                     : "memory");
    }
}

// ---------------- launch -------------------------------------------------------
static inline int smem_sz(int K, int N) { return 4608 + K * N * 4 + 16384; }

extern "C" void kernel_launch(void* const* d_in, const int* in_sizes, int n_in,
                              void* d_out, int out_size)
{
    const float* m_input  = (const float*)d_in[0];
    const float* rbf      = (const float*)d_in[1];
    const float* sbf      = (const float*)d_in[2];
    const float* Wkj      = (const float*)d_in[3];
    const float* bkj      = (const float*)d_in[4];
    const float* Wrbf1    = (const float*)d_in[5];
    const float* Wrbf2    = (const float*)d_in[6];
    const float* Wdown    = (const float*)d_in[7];
    const float* Wsbf1    = (const float*)d_in[8];
    const float* Wsbf2    = (const float*)d_in[9];
    const float* Wup      = (const float*)d_in[10];
    const float* Wji      = (const float*)d_in[11];
    const float* bji      = (const float*)d_in[12];
    const float* rb1_W1   = (const float*)d_in[13];
    const float* rb1_b1   = (const float*)d_in[14];
    const float* rb1_W2   = (const float*)d_in[15];
    const float* rb1_b2   = (const float*)d_in[16];
    const float* Wfin     = (const float*)d_in[17];
    const float* bfin     = (const float*)d_in[18];
    const float* ra1_W1   = (const float*)d_in[19];
    const float* ra1_b1   = (const float*)d_in[20];
    const float* ra1_W2   = (const float*)d_in[21];
    const float* ra1_b2   = (const float*)d_in[22];
    const float* ra2_W1   = (const float*)d_in[23];
    const float* ra2_b1   = (const float*)d_in[24];
    const float* ra2_W2   = (const float*)d_in[25];
    const float* ra2_b2   = (const float*)d_in[26];
    const int*   red_ji   = (const int*)  d_in[27];
    const int*   exp_kj   = (const int*)  d_in[28];

    const int E = in_sizes[0] / D_;
    const int T = in_sizes[27];

    float *t1, *m, *down, *agg, *hrbf, *hsbf;
    uint32_t *wf;
    cudaGetSymbolAddress((void**)&t1,   g_t1);
    cudaGetSymbolAddress((void**)&m,    g_mbuf);
    cudaGetSymbolAddress((void**)&down, g_down);
    cudaGetSymbolAddress((void**)&agg,  g_agg);
    cudaGetSymbolAddress((void**)&hrbf, g_hrbf);
    cudaGetSymbolAddress((void**)&hsbf, g_hsbf);
    cudaGetSymbolAddress((void**)&wf,   g_wfrag);

    float* outp = (float*)d_out;
    const int grid = (E + 127) / 128;

    const int S_FF = smem_sz(128, 128);   // 86528
    const int S_FD = smem_sz(128, 64);    // 53760
    const int S_DF = smem_sz(64, 128);    // 53760
    cudaFuncSetAttribute((const void*)gemm_mma<128,128,EP_SILU>,        cudaFuncAttributeMaxDynamicSharedMemorySize, S_FF);
    cudaFuncSetAttribute((const void*)gemm_mma<128,128,EP_SILU_ADD>,    cudaFuncAttributeMaxDynamicSharedMemorySize, S_FF);
    cudaFuncSetAttribute((const void*)gemm_mma<128,128,EP_SILU_MULRBF>, cudaFuncAttributeMaxDynamicSharedMemorySize, S_FF);
    cudaFuncSetAttribute((const void*)gemm_mma<128,64, EP_SILU>,        cudaFuncAttributeMaxDynamicSharedMemorySize, S_FD);
    cudaFuncSetAttribute((const void*)gemm_mma<64,128, EP_SILU>,        cudaFuncAttributeMaxDynamicSharedMemorySize, S_DF);

    // ---- weight fragment prep (split + permute + interleave) ----
    k_wfrag<<<16, 256>>>(Wkj,    128, 128, wf + OFF_Wkj);
    k_wfrag<<<16, 256>>>(Wji,    128, 128, wf + OFF_Wji);
    k_wfrag<<<16, 256>>>(rb1_W1, 128, 128, wf + OFF_rb1W1);
    k_wfrag<<<16, 256>>>(rb1_W2, 128, 128, wf + OFF_rb1W2);
    k_wfrag<<<16, 256>>>(Wfin,   128, 128, wf + OFF_Wfin);
    k_wfrag<<<16, 256>>>(ra1_W1, 128, 128, wf + OFF_ra1W1);
    k_wfrag<<<16, 256>>>(ra1_W2, 128, 128, wf + OFF_ra1W2);
    k_wfrag<<<16, 256>>>(ra2_W1, 128, 128, wf + OFF_ra2W1);
    k_wfrag<<<16, 256>>>(ra2_W2, 128, 128, wf + OFF_ra2W2);
    k_wfrag<<<8, 256>>>(Wdown,   128, 64,  wf + OFF_Wdown);
    k_wfrag<<<8, 256>>>(Wup,     64,  128, wf + OFF_Wup);

    // 1. zero aggregation buffer
    {
        int n4 = (E * DA_) / 4;
        k_zero<<<(n4 + 255) / 256, 256>>>((float4*)agg, n4);
    }
    // 2-3. small basis projections
    k_hrbf<<<(E + 255) / 256, 256>>>(rbf, Wrbf1, hrbf, E);
    k_hsbf<<<(T + 255) / 256, 256>>>(sbf, Wsbf1, hsbf, T);

    // 4. m_ang = silu(m_input @ Wkj + bkj) * (h_rbf @ Wrbf2)   -> t1 [E,128]
    gemm_mma<128,128,EP_SILU_MULRBF><<<grid, 256, S_FF>>>(
        m_input, wf + OFF_Wkj, bkj, nullptr, hrbf, Wrbf2, t1, E);
    // 5. down = silu(t1 @ Wdown)                               -> down [E,64]
    gemm_mma<128,64,EP_SILU><<<grid, 256, S_FD>>>(
        t1, wf + OFF_Wdown, nullptr, nullptr, nullptr, nullptr, down, E);
    // 6. triplet gather / sbf-mod / scatter-add                -> agg [E,64]
    k_triplet<<<2048, 256>>>(hsbf, Wsbf2, exp_kj, red_ji, down, agg, T);
    // 7. prop = silu(agg @ Wup)                                -> t1 [E,128]
    gemm_mma<64,128,EP_SILU><<<grid, 256, S_DF>>>(
        agg, wf + OFF_Wup, nullptr, nullptr, nullptr, nullptr, t1, E);
    // 8. m = silu(m_input @ Wji + bji) + prop
    gemm_mma<128,128,EP_SILU_ADD><<<grid, 256, S_FF>>>(
        m_input, wf + OFF_Wji, bji, t1, nullptr, nullptr, m, E);
    // 9-10. residual block b1
    gemm_mma<128,128,EP_SILU><<<grid, 256, S_FF>>>(
        m, wf + OFF_rb1W1, rb1_b1, nullptr, nullptr, nullptr, t1, E);
    gemm_mma<128,128,EP_SILU_ADD><<<grid, 256, S_FF>>>(
        t1, wf + OFF_rb1W2, rb1_b2, m, nullptr, nullptr, m, E);
    // 11. m = silu(m @ Wfin + bfin) + m_input
    gemm_mma<128,128,EP_SILU_ADD><<<grid, 256, S_FF>>>(
        m, wf + OFF_Wfin, bfin, m_input, nullptr, nullptr, m, E);
    // 12-13. residual block a1
    gemm_mma<128,128,EP_SILU><<<grid, 256, S_FF>>>(
        m, wf + OFF_ra1W1, ra1_b1, nullptr, nullptr, nullptr, t1, E);
    gemm_mma<128,128,EP_SILU_ADD><<<grid, 256, S_FF>>>(
        t1, wf + OFF_ra1W2, ra1_b2, m, nullptr, nullptr, m, E);
    // 14-15. residual block a2 -> final output
    gemm_mma<128,128,EP_SILU><<<grid, 256, S_FF>>>(
        m, wf + OFF_ra2W1, ra2_b1, nullptr, nullptr, nullptr, t1, E);
    gemm_mma<128,128,EP_SILU_ADD><<<grid, 256, S_FF>>>(
        t1, wf + OFF_ra2W2, ra2_b2, m, nullptr, nullptr, outp, E);
}

// round 8
// speedup vs baseline: 2.0126x; 1.2519x over previous
#include <cuda_runtime.h>
#include <cuda_bf16.h>
#include <cstdint>

// ---------------- problem constants (fixed for this dataset) ----------------
#define D_    128
#define DA_   64
#define DB_   8
#define NR_   6
#define NS_   42
#define E_MAX 200000
#define T_MAX 1600000
#define RT_MAX 12504            // row-tiles of 16 covering grid*128 rows

// ---------------- scratch (static device globals; no allocation) ------------
// fragment-layout activation buffers: plane-major {hi, lo}, quad index
// ((rt*KT + s)*32 + lane), KT = cols/16
__device__ __align__(16) uint4 g_fT1 [(size_t)2 * RT_MAX * 8 * 32];
__device__ __align__(16) uint4 g_fM  [(size_t)2 * RT_MAX * 8 * 32];
__device__ __align__(16) uint4 g_fX  [(size_t)2 * RT_MAX * 8 * 32];
__device__ __align__(16) uint4 g_fMin[(size_t)2 * RT_MAX * 8 * 32];
__device__ __align__(16) uint4 g_fAgg[(size_t)2 * RT_MAX * 4 * 32];
__device__ __align__(16) float g_down[(size_t)E_MAX * DA_];
__device__ __align__(16) float g_agg [(size_t)E_MAX * DA_];
__device__ __align__(16) float g_hrbf[(size_t)E_MAX * DB_];
__device__ __align__(16) float g_hsbf[(size_t)T_MAX * DB_];
// prepacked weight fragments, hi/lo interleaved per uint4: {bh0,bh1,bl0,bl1}
__device__ __align__(16) uint32_t g_wfrag[163840];

#define OFF_Wkj    0
#define OFF_Wji    16384
#define OFF_rb1W1  32768
#define OFF_rb1W2  49152
#define OFF_Wfin   65536
#define OFF_ra1W1  81920
#define OFF_ra1W2  98304
#define OFF_ra2W1  114688
#define OFF_ra2W2  131072
#define OFF_Wdown  147456
#define OFF_Wup    155648

// ---------------- helpers ----------------------------------------------------
__device__ __forceinline__ float silu_f(float x) {
    return x / (1.0f + __expf(-x));
}
__device__ __forceinline__ void splitpack2(float x0, float x1,
                                           uint32_t& hi, uint32_t& lo) {
    asm("cvt.rn.bf16x2.f32 %0, %1, %2;" : "=r"(hi) : "f"(x1), "f"(x0));
    float f0 = __uint_as_float(hi << 16);
    float f1 = __uint_as_float(hi & 0xFFFF0000u);
    float l0 = x0 - f0;
    float l1 = x1 - f1;
    asm("cvt.rn.bf16x2.f32 %0, %1, %2;" : "=r"(lo) : "f"(l1), "f"(l0));
}
__device__ __forceinline__ float lo16f(uint32_t u) { return __uint_as_float(u << 16); }
__device__ __forceinline__ float hi16f(uint32_t u) { return __uint_as_float(u & 0xFFFF0000u); }

__device__ __forceinline__ void mma_bf16(float* c, const uint32_t* a, const uint32_t* b) {
    asm volatile(
        "mma.sync.aligned.m16n8k16.row.col.f32.bf16.bf16.f32 "
        "{%0,%1,%2,%3}, {%4,%5,%6,%7}, {%8,%9}, {%0,%1,%2,%3};"
        : "+f"(c[0]), "+f"(c[1]), "+f"(c[2]), "+f"(c[3])
        : "r"(a[0]), "r"(a[1]), "r"(a[2]), "r"(a[3]), "r"(b[0]), "r"(b[1]));
}
__device__ __forceinline__ void cp_async16(uint32_t saddr, const void* gaddr) {
    asm volatile("cp.async.cg.shared.global [%0], [%1], 16;"
                 :: "r"(saddr), "l"(gaddr));
}
#define CP_COMMIT() asm volatile("cp.async.commit_group;" ::: "memory")
#define CP_WAIT(n)  asm volatile("cp.async.wait_group %0;" :: "n"(n) : "memory")
__device__ __forceinline__ uint32_t smem_u32(const void* p) {
    uint32_t a;
    asm("{ .reg .u64 t; cvta.to.shared.u64 t, %1; cvt.u32.u64 %0, t; }" : "=r"(a) : "l"(p));
    return a;
}

// ---------------- epilogue modes ---------------------------------------------
#define EP_SILU        0
#define EP_SILU_ADDFR  1   // + res (fragment hi/lo planes)
#define EP_SILU_ADDF32 2   // + res (fp32 row-major)
#define EP_SILU_MULRBF 3   // * (hrbf @ Wrbf2)

// ---------------- tensor-core GEMM -------------------------------------------
// A is pre-split bf16 hi/lo fragment planes in global; cp.async 4-stage pipe.
// W fragments (hi/lo interleaved) resident in smem. 3-term bf16 product.
// OUTF=true: store fragment hi/lo planes (next GEMM's A). false: fp32 rows.
template <int KT, int NT, int MODE, bool OUTF>
__global__ void __launch_bounds__(256, 2) gemm_mma(
    const uint4* __restrict__ Ah, const uint4* __restrict__ Al,
    const uint32_t* __restrict__ wfrag,
    const float* __restrict__ bias,
    const uint4* __restrict__ resH, const uint4* __restrict__ resL,
    const float* __restrict__ resF,
    const float* __restrict__ hrbf, const float* __restrict__ wrbf2,
    float* __restrict__ outF, uint4* __restrict__ outH, uint4* __restrict__ outL,
    int E)
{
    constexpr int NKS = KT;                // k16 steps
    constexpr int NTN = NT / 8;            // B n-tiles per CTA
    constexpr int NWN = NT / 32;           // n-tiles per warp
    constexpr int SM_B = 4608;
    constexpr int B_BYTES = KT * NT * 64;
    constexpr int SM_A = SM_B + B_BYTES;   // 4 stages x 512 quads x 16B

    extern __shared__ char smem[];
    const uint32_t sb = smem_u32(smem);
    float* sBias = (float*)smem;
    float* sW2   = (float*)(smem + 512);

    const int tid  = threadIdx.x;
    const int lane = tid & 31;
    const int wid  = tid >> 5;
    const int warpM = wid >> 2;
    const int warpN = wid & 3;
    const int rt0 = blockIdx.x * 8;

    // ---- B fragment async copy ----
    {
        constexpr int CNT4 = B_BYTES / 16;
        const uint4* src = (const uint4*)wfrag;
#pragma unroll
        for (int i = 0; i < CNT4 / 256; i++) {
            int f = tid + i * 256;
            cp_async16(sb + SM_B + f * 16, src + f);
        }
    }
    // ---- A stage prefetch: 512 quads (2 planes x 8 rt x 32 lanes) ----
    auto prefA = [&](int s, int buf) {
#pragma unroll
        for (int i = 0; i < 2; i++) {
            int f   = tid + i * 256;
            int pl  = f >> 8;
            int rtl = (f >> 5) & 7;
            int ln  = f & 31;
            const uint4* src = (pl ? Al : Ah) + ((rt0 + rtl) * KT + s) * 32 + ln;
            cp_async16(sb + SM_A + buf * 8192 + f * 16, src);
        }
    };
    prefA(0, 0); CP_COMMIT();                 // group0 = B + A0
    if (NKS > 1) { prefA(1, 1); CP_COMMIT(); }

    if (tid < NT) sBias[tid] = bias ? bias[tid] : 0.0f;
    if (MODE == EP_SILU_MULRBF)
        for (int i = tid; i < DB_ * NT; i += 256) sW2[i] = wrbf2[i];

    float acc[4][NWN][4];
#pragma unroll
    for (int mt = 0; mt < 4; mt++)
#pragma unroll
        for (int nt = 0; nt < NWN; nt++)
#pragma unroll
            for (int j = 0; j < 4; j++) acc[mt][nt][j] = 0.f;

#pragma unroll
    for (int s = 0; s < NKS; s++) {
        if (s + 2 < NKS) { prefA(s + 2, (s + 2) & 3); CP_COMMIT(); }
        if (s + 2 < NKS)      CP_WAIT(2);
        else if (s + 1 < NKS) CP_WAIT(1);
        else                  CP_WAIT(0);
        __syncthreads();

        const int buf = s & 3;
        const char* ab = smem + SM_A + buf * 8192;
        uint4 ahi[4], alo[4];
#pragma unroll
        for (int mt = 0; mt < 4; mt++) {
            int gm = warpM * 4 + mt;
            ahi[mt] = *(const uint4*)(ab + (gm * 32 + lane) * 16);
            alo[mt] = *(const uint4*)(ab + ((8 + gm) * 32 + lane) * 16);
        }
#pragma unroll
        for (int nt = 0; nt < NWN; nt++) {
            int gt = warpN * NWN + nt;
            uint4 bq = *(const uint4*)(smem + SM_B + (((s * NTN) + gt) * 32 + lane) * 16);
            uint32_t bh[2] = {bq.x, bq.y};
            uint32_t bl[2] = {bq.z, bq.w};
#pragma unroll
            for (int mt = 0; mt < 4; mt++) {
                mma_bf16(acc[mt][nt], (const uint32_t*)&ahi[mt], bh);
                mma_bf16(acc[mt][nt], (const uint32_t*)&ahi[mt], bl);
                mma_bf16(acc[mt][nt], (const uint32_t*)&alo[mt], bh);
            }
        }
    }

    // ---- epilogue ----
#pragma unroll
    for (int mt = 0; mt < 4; mt++) {
        const int rtg = rt0 + warpM * 4 + mt;
        if (rtg * 16 >= E) continue;

        float o[NWN][4];
#pragma unroll
        for (int nt = 0; nt < NWN; nt++) {
            int col = warpN * NWN * 8 + nt * 8 + 2 * (lane & 3);
#pragma unroll
            for (int half = 0; half < 2; half++) {
                o[nt][half * 2 + 0] = silu_f(acc[mt][nt][half * 2 + 0] + sBias[col]);
                o[nt][half * 2 + 1] = silu_f(acc[mt][nt][half * 2 + 1] + sBias[col + 1]);
            }
        }
        if (MODE == EP_SILU_MULRBF) {
            int rlo = rtg * 16 + (lane >> 2);
            float4 a0 = __ldg((const float4*)(hrbf + (size_t)rlo * DB_));
            float4 a1 = __ldg((const float4*)(hrbf + (size_t)rlo * DB_ + 4));
            float4 b0 = __ldg((const float4*)(hrbf + (size_t)(rlo + 8) * DB_));
            float4 b1 = __ldg((const float4*)(hrbf + (size_t)(rlo + 8) * DB_ + 4));
            float hA[8] = {a0.x, a0.y, a0.z, a0.w, a1.x, a1.y, a1.z, a1.w};
            float hB[8] = {b0.x, b0.y, b0.z, b0.w, b1.x, b1.y, b1.z, b1.w};
#pragma unroll
            for (int nt = 0; nt < NWN; nt++) {
                int col = warpN * NWN * 8 + nt * 8 + 2 * (lane & 3);
                float r0 = 0.f, r1 = 0.f, r2 = 0.f, r3 = 0.f;
#pragma unroll
                for (int j = 0; j < DB_; j++) {
                    float w0 = sW2[j * NT + col], w1 = sW2[j * NT + col + 1];
                    r0 += hA[j] * w0; r1 += hA[j] * w1;
                    r2 += hB[j] * w0; r3 += hB[j] * w1;
                }
                o[nt][0] *= r0; o[nt][1] *= r1; o[nt][2] *= r2; o[nt][3] *= r3;
            }
        } else if (MODE == EP_SILU_ADDF32) {
#pragma unroll
            for (int nt = 0; nt < NWN; nt++) {
                int col = warpN * NWN * 8 + nt * 8 + 2 * (lane & 3);
#pragma unroll
                for (int half = 0; half < 2; half++) {
                    int row = rtg * 16 + (lane >> 2) + half * 8;
                    float2 rr = __ldg((const float2*)(resF + (size_t)row * NT + col));
                    o[nt][half * 2 + 0] += rr.x;
                    o[nt][half * 2 + 1] += rr.y;
                }
            }
        } else if (MODE == EP_SILU_ADDFR) {
#pragma unroll
            for (int j = 0; j < NWN / 2; j++) {
                int q = ((rtg * (NT / 16)) + warpN * (NWN / 2) + j) * 32 + lane;
                uint4 rh = __ldg(resH + q);
                uint4 rl = __ldg(resL + q);
                o[2 * j    ][0] += lo16f(rh.x) + lo16f(rl.x);
                o[2 * j    ][1] += hi16f(rh.x) + hi16f(rl.x);
                o[2 * j    ][2] += lo16f(rh.y) + lo16f(rl.y);
                o[2 * j    ][3] += hi16f(rh.y) + hi16f(rl.y);
                o[2 * j + 1][0] += lo16f(rh.z) + lo16f(rl.z);
                o[2 * j + 1][1] += hi16f(rh.z) + hi16f(rl.z);
                o[2 * j + 1][2] += lo16f(rh.w) + lo16f(rl.w);
                o[2 * j + 1][3] += hi16f(rh.w) + hi16f(rl.w);
            }
        }

        if (OUTF) {
            // pack into next-GEMM A fragments (C-frag == A-frag layout)
#pragma unroll
            for (int j = 0; j < NWN / 2; j++) {
                uint4 h, l;
                splitpack2(o[2 * j][0],     o[2 * j][1],     h.x, l.x);
                splitpack2(o[2 * j][2],     o[2 * j][3],     h.y, l.y);
                splitpack2(o[2 * j + 1][0], o[2 * j + 1][1], h.z, l.z);
                splitpack2(o[2 * j + 1][2], o[2 * j + 1][3], h.w, l.w);
                int q = ((rtg * (NT / 16)) + warpN * (NWN / 2) + j) * 32 + lane;
                outH[q] = h;
                outL[q] = l;
            }
        } else {
#pragma unroll
            for (int nt = 0; nt < NWN; nt++) {
                int col = warpN * NWN * 8 + nt * 8 + 2 * (lane & 3);
#pragma unroll
                for (int half = 0; half < 2; half++) {
                    int row = rtg * 16 + (lane >> 2) + half * 8;
                    if (row < E)
                        *(float2*)(outF + (size_t)row * NT + col) =
                            make_float2(o[nt][half * 2], o[nt][half * 2 + 1]);
                }
            }
        }
    }
}

// ---------------- activation split: fp32 rows -> fragment hi/lo planes --------
__global__ void __launch_bounds__(256) k_asplit(
    const float* __restrict__ src, int E, int KT,
    uint4* __restrict__ hi, uint4* __restrict__ lo)
{
    int idx = blockIdx.x * 256 + threadIdx.x;   // quad index
    int RT = E / 16;
    if (idx >= RT * KT * 32) return;
    int lane = idx & 31;
    int s    = (idx >> 5) % KT;
    int rt   = idx / (32 * KT);
    int cols = KT * 16;
    int r0 = rt * 16 + (lane >> 2);
    int k0 = s * 16 + 2 * (lane & 3);
    const float* b0 = src + (size_t)r0 * cols + k0;
    const float* b1 = b0 + (size_t)8 * cols;
    float2 v0 = *(const float2*)(b0);
    float2 v1 = *(const float2*)(b1);
    float2 v2 = *(const float2*)(b0 + 8);
    float2 v3 = *(const float2*)(b1 + 8);
    uint4 h, l;
    splitpack2(v0.x, v0.y, h.x, l.x);
    splitpack2(v1.x, v1.y, h.y, l.y);
    splitpack2(v2.x, v2.y, h.z, l.z);
    splitpack2(v3.x, v3.y, h.w, l.w);
    hi[idx] = h;
    lo[idx] = l;
}

// ---------------- merged weight fragment prep (all 11 weights) ----------------
__global__ void __launch_bounds__(256) k_wfrag_all(
    const float* w0, const float* w1, const float* w2, const float* w3,
    const float* w4, const float* w5, const float* w6, const float* w7,
    const float* w8, const float* w9, const float* w10,
    uint32_t* __restrict__ outv)
{
    const float* Ws[11] = {w0, w1, w2, w3, w4, w5, w6, w7, w8, w9, w10};
    int b = blockIdx.x;
    const float* W;
    int K, N, off, lidx;
    if (b < 144) {
        int w = b / 16;
        W = Ws[w]; K = 128; N = 128;
        off = w * 16384;
        lidx = (b % 16) * 256 + threadIdx.x;
    } else if (b < 152) {
        W = Ws[9]; K = 128; N = 64; off = OFF_Wdown;
        lidx = (b - 144) * 256 + threadIdx.x;
    } else {
        W = Ws[10]; K = 64; N = 128; off = OFF_Wup;
        lidx = (b - 152) * 256 + threadIdx.x;
    }
    int total = (K / 16) * (N / 8) * 32;
    if (lidx >= total) return;
    int lane = lidx & 31;
    int st   = lidx >> 5;
    int t    = st % (N / 8);
    int s    = st / (N / 8);
    int q = lane & 3, r = lane >> 2;
    int n  = t * 8 + r;
    int k0 = s * 16 + 2 * q;
    float a00 = __ldg(W + (size_t)k0 * N + n);
    float a01 = __ldg(W + (size_t)(k0 + 1) * N + n);
    float a10 = __ldg(W + (size_t)(k0 + 8) * N + n);
    float a11 = __ldg(W + (size_t)(k0 + 9) * N + n);
    uint32_t h0, l0, h1, l1;
    splitpack2(a00, a01, h0, l0);
    splitpack2(a10, a11, h1, l1);
    ((uint4*)(outv + off))[lidx] = make_uint4(h0, h1, l0, l1);
}

// ---------------- small kernels (validated) ------------------------------------
__global__ void __launch_bounds__(256) k_zero(float4* __restrict__ p, int n4) {
    int i = blockIdx.x * blockDim.x + threadIdx.x;
    if (i < n4) p[i] = make_float4(0.f, 0.f, 0.f, 0.f);
}

__global__ void __launch_bounds__(256) k_hrbf(
    const float* __restrict__ rbf, const float* __restrict__ w1,
    float* __restrict__ out, int E)
{
    __shared__ float sw[NR_ * DB_];
    if (threadIdx.x < NR_ * DB_) sw[threadIdx.x] = w1[threadIdx.x];
    __syncthreads();
    int r = blockIdx.x * blockDim.x + threadIdx.x;
    if (r >= E) return;
    float x[NR_];
#pragma unroll
    for (int j = 0; j < NR_; j++) x[j] = __ldg(rbf + (size_t)r * NR_ + j);
    float h[DB_];
#pragma unroll
    for (int k = 0; k < DB_; k++) h[k] = 0.f;
#pragma unroll
    for (int j = 0; j < NR_; j++)
#pragma unroll
        for (int k = 0; k < DB_; k++) h[k] += x[j] * sw[j * DB_ + k];
    float4* op = (float4*)(out + (size_t)r * DB_);
    op[0] = make_float4(h[0], h[1], h[2], h[3]);
    op[1] = make_float4(h[4], h[5], h[6], h[7]);
}

__global__ void __launch_bounds__(256) k_hsbf(
    const float* __restrict__ sbf, const float* __restrict__ w1,
    float* __restrict__ out, int T)
{
    __shared__ float st[256 * NS_];
    __shared__ float sw[NS_ * DB_];
    for (int i = threadIdx.x; i < NS_ * DB_; i += 256) sw[i] = w1[i];

    int base = blockIdx.x * 256;
    int n = T - base; if (n > 256) n = 256;
    int total = n * NS_;
    for (int i = threadIdx.x; i < total; i += 256)
        st[i] = sbf[(size_t)base * NS_ + i];
    __syncthreads();

    int r = threadIdx.x;
    if (r >= n) return;
    const float* x = &st[r * NS_];
    float h[DB_];
#pragma unroll
    for (int k = 0; k < DB_; k++) h[k] = 0.f;
#pragma unroll
    for (int j = 0; j < NS_; j++) {
        float xv = x[j];
#pragma unroll
        for (int k = 0; k < DB_; k++) h[k] += xv * sw[j * DB_ + k];
    }
    float4* op = (float4*)(out + (size_t)(base + r) * DB_);
    op[0] = make_float4(h[0], h[1], h[2], h[3]);
    op[1] = make_float4(h[4], h[5], h[6], h[7]);
}

__global__ void __launch_bounds__(256) k_triplet(
    const float* __restrict__ hsbf, const float* __restrict__ wsbf2,
    const int* __restrict__ exp_kj, const int* __restrict__ red_ji,
    const float* __restrict__ down, float* __restrict__ agg, int T)
{
    __shared__ float sw[DB_ * DA_];
    for (int i = threadIdx.x; i < DB_ * DA_; i += 256) sw[i] = wsbf2[i];
    __syncthreads();

    const int q = threadIdx.x & 15;
    float w[DB_][4];
#pragma unroll
    for (int i = 0; i < DB_; i++)
#pragma unroll
        for (int j = 0; j < 4; j++) w[i][j] = sw[i * DA_ + q * 4 + j];

    int t = (blockIdx.x * blockDim.x + threadIdx.x) >> 4;
    const int stride = (gridDim.x * blockDim.x) >> 4;

    for (; t < T; t += stride) {
        int e = __ldg(exp_kj + t);
        int g = __ldg(red_ji + t);
        const float4* hp = (const float4*)(hsbf + (size_t)t * DB_);
        float4 h0 = __ldg(hp), h1 = __ldg(hp + 1);
        float hh[8] = {h0.x, h0.y, h0.z, h0.w, h1.x, h1.y, h1.z, h1.w};

        float s0 = 0.f, s1 = 0.f, s2 = 0.f, s3 = 0.f;
#pragma unroll
        for (int i = 0; i < DB_; i++) {
            s0 += hh[i] * w[i][0];
            s1 += hh[i] * w[i][1];
            s2 += hh[i] * w[i][2];
            s3 += hh[i] * w[i][3];
        }
        float4 a = __ldg((const float4*)(down + (size_t)e * DA_ + q * 4));
        float vx = a.x * s0, vy = a.y * s1, vz = a.z * s2, vw = a.w * s3;

        float* dst = agg + (size_t)g * DA_ + q * 4;
        asm volatile("red.global.add.v4.f32 [%0], {%1, %2, %3, %4};"
                     :: "l"(dst), "f"(vx), "f"(vy), "f"(vz), "f"(vw)
                     : "memory");
    }
}

// ---------------- launch -------------------------------------------------------
static inline int smem_sz(int KT, int NT) { return 4608 + KT * NT * 64 + 32768; }

extern "C" void kernel_launch(void* const* d_in, const int* in_sizes, int n_in,
                              void* d_out, int out_size)
{
    const float* m_input  = (const float*)d_in[0];
    const float* rbf      = (const float*)d_in[1];
    const float* sbf      = (const float*)d_in[2];
    const float* Wkj      = (const float*)d_in[3];
    const float* bkj      = (const float*)d_in[4];
    const float* Wrbf1    = (const float*)d_in[5];
    const float* Wrbf2    = (const float*)d_in[6];
    const float* Wdown    = (const float*)d_in[7];
    const float* Wsbf1    = (const float*)d_in[8];
    const float* Wsbf2    = (const float*)d_in[9];
    const float* Wup      = (const float*)d_in[10];
    const float* Wji      = (const float*)d_in[11];
    const float* bji      = (const float*)d_in[12];
    const float* rb1_W1   = (const float*)d_in[13];
    const float* rb1_b1   = (const float*)d_in[14];
    const float* rb1_W2   = (const float*)d_in[15];
    const float* rb1_b2   = (const float*)d_in[16];
    const float* Wfin     = (const float*)d_in[17];
    const float* bfin     = (const float*)d_in[18];
    const float* ra1_W1   = (const float*)d_in[19];
    const float* ra1_b1   = (const float*)d_in[20];
    const float* ra1_W2   = (const float*)d_in[21];
    const float* ra1_b2   = (const float*)d_in[22];
    const float* ra2_W1   = (const float*)d_in[23];
    const float* ra2_b1   = (const float*)d_in[24];
    const float* ra2_W2   = (const float*)d_in[25];
    const float* ra2_b2   = (const float*)d_in[26];
    const int*   red_ji   = (const int*)  d_in[27];
    const int*   exp_kj   = (const int*)  d_in[28];

    const int E = in_sizes[0] / D_;
    const int T = in_sizes[27];

    uint4 *fT1, *fM, *fX, *fMin, *fAgg;
    float *down, *agg, *hrbf, *hsbf;
    uint32_t *wf;
    cudaGetSymbolAddress((void**)&fT1,  g_fT1);
    cudaGetSymbolAddress((void**)&fM,   g_fM);
    cudaGetSymbolAddress((void**)&fX,   g_fX);
    cudaGetSymbolAddress((void**)&fMin, g_fMin);
    cudaGetSymbolAddress((void**)&fAgg, g_fAgg);
    cudaGetSymbolAddress((void**)&down, g_down);
    cudaGetSymbolAddress((void**)&agg,  g_agg);
    cudaGetSymbolAddress((void**)&hrbf, g_hrbf);
    cudaGetSymbolAddress((void**)&hsbf, g_hsbf);
    cudaGetSymbolAddress((void**)&wf,   g_wfrag);

    const size_t P8 = (size_t)RT_MAX * 8 * 32;   // plane stride (quads), KT=8
    const size_t P4 = (size_t)RT_MAX * 4 * 32;   // KT=4

    float* outp = (float*)d_out;
    const int grid = (E + 127) / 128;

    const int S_FF = smem_sz(8, 128);   // 102912
    const int S_FD = smem_sz(8, 64);    // 70144
    const int S_DF = smem_sz(4, 128);   // 70144
    cudaFuncSetAttribute((const void*)gemm_mma<8,128,EP_SILU,true>,        cudaFuncAttributeMaxDynamicSharedMemorySize, S_FF);
    cudaFuncSetAttribute((const void*)gemm_mma<8,128,EP_SILU_ADDFR,true>,  cudaFuncAttributeMaxDynamicSharedMemorySize, S_FF);
    cudaFuncSetAttribute((const void*)gemm_mma<8,128,EP_SILU_ADDFR,false>, cudaFuncAttributeMaxDynamicSharedMemorySize, S_FF);
    cudaFuncSetAttribute((const void*)gemm_mma<8,128,EP_SILU_ADDF32,true>, cudaFuncAttributeMaxDynamicSharedMemorySize, S_FF);
    cudaFuncSetAttribute((const void*)gemm_mma<8,128,EP_SILU_MULRBF,true>, cudaFuncAttributeMaxDynamicSharedMemorySize, S_FF);
    cudaFuncSetAttribute((const void*)gemm_mma<8,64, EP_SILU,false>,       cudaFuncAttributeMaxDynamicSharedMemorySize, S_FD);
    cudaFuncSetAttribute((const void*)gemm_mma<4,128,EP_SILU,true>,        cudaFuncAttributeMaxDynamicSharedMemorySize, S_DF);

    // ---- prep ----
    k_wfrag_all<<<160, 256>>>(Wkj, Wji, rb1_W1, rb1_W2, Wfin,
                              ra1_W1, ra1_W2, ra2_W1, ra2_W2, Wdown, Wup, wf);
    {
        int n4 = (E * DA_) / 4;
        k_zero<<<(n4 + 255) / 256, 256>>>((float4*)agg, n4);
    }
    k_hrbf<<<(E + 255) / 256, 256>>>(rbf, Wrbf1, hrbf, E);
    k_hsbf<<<(T + 255) / 256, 256>>>(sbf, Wsbf1, hsbf, T);
    {
        int nq = (E / 16) * 8 * 32;
        k_asplit<<<(nq + 255) / 256, 256>>>(m_input, E, 8, fMin, fMin + P8);
    }

    // 4. t1 = silu(m_input @ Wkj + bkj) * rbfmod           [frag]
    gemm_mma<8,128,EP_SILU_MULRBF,true><<<grid, 256, S_FF>>>(
        fMin, fMin + P8, wf + OFF_Wkj, bkj,
        nullptr, nullptr, nullptr, hrbf, Wrbf2,
        nullptr, fT1, fT1 + P8, E);
    // 5. down = silu(t1 @ Wdown)                           [fp32]
    gemm_mma<8,64,EP_SILU,false><<<grid, 256, S_FD>>>(
        fT1, fT1 + P8, wf + OFF_Wdown, nullptr,
        nullptr, nullptr, nullptr, nullptr, nullptr,
        down, nullptr, nullptr, E);
    // 6. triplet -> agg (fp32), then split
    k_triplet<<<2048, 256>>>(hsbf, Wsbf2, exp_kj, red_ji, down, agg, T);
    {
        int nq = (E / 16) * 4 * 32;
        k_asplit<<<(nq + 255) / 256, 256>>>(agg, E, 4, fAgg, fAgg + P4);
    }
    // 7. prop = silu(agg @ Wup)                            [frag] -> fT1
    gemm_mma<4,128,EP_SILU,true><<<grid, 256, S_DF>>>(
        fAgg, fAgg + P4, wf + OFF_Wup, nullptr,
        nullptr, nullptr, nullptr, nullptr, nullptr,
        nullptr, fT1, fT1 + P8, E);
    // 8. m = silu(m_input @ Wji + bji) + prop              [frag] -> fM
    gemm_mma<8,128,EP_SILU_ADDFR,true><<<grid, 256, S_FF>>>(
        fMin, fMin + P8, wf + OFF_Wji, bji,
        fT1, fT1 + P8, nullptr, nullptr, nullptr,
        nullptr, fM, fM + P8, E);
    // 9-10. residual block b1: fM -> fX
    gemm_mma<8,128,EP_SILU,true><<<grid, 256, S_FF>>>(
        fM, fM + P8, wf + OFF_rb1W1, rb1_b1,
        nullptr, nullptr, nullptr, nullptr, nullptr,
        nullptr, fT1, fT1 + P8, E);
    gemm_mma<8,128,EP_SILU_ADDFR,true><<<grid, 256, S_FF>>>(
        fT1, fT1 + P8, wf + OFF_rb1W2, rb1_b2,
        fM, fM + P8, nullptr, nullptr, nullptr,
        nullptr, fX, fX + P8, E);
    // 11. m = silu(fX @ Wfin + bfin) + m_input (fp32)      [frag] -> fM
    gemm_mma<8,128,EP_SILU_ADDF32,true><<<grid, 256, S_FF>>>(
        fX, fX + P8, wf + OFF_Wfin, bfin,
        nullptr, nullptr, m_input, nullptr, nullptr,
        nullptr, fM, fM + P8, E);
    // 12-13. residual block a1: fM -> fX
    gemm_mma<8,128,EP_SILU,true><<<grid, 256, S_FF>>>(
        fM, fM + P8, wf + OFF_ra1W1, ra1_b1,
        nullptr, nullptr, nullptr, nullptr, nullptr,
        nullptr, fT1, fT1 + P8, E);
    gemm_mma<8,128,EP_SILU_ADDFR,true><<<grid, 256, S_FF>>>(
        fT1, fT1 + P8, wf + OFF_ra1W2, ra1_b2,
        fM, fM + P8, nullptr, nullptr, nullptr,
        nullptr, fX, fX + P8, E);
    // 14-15. residual block a2: fX -> d_out (fp32)
    gemm_mma<8,128,EP_SILU,true><<<grid, 256, S_FF>>>(
        fX, fX + P8, wf + OFF_ra2W1, ra2_b1,
        nullptr, nullptr, nullptr, nullptr, nullptr,
        nullptr, fT1, fT1 + P8, E);
    gemm_mma<8,128,EP_SILU_ADDFR,false><<<grid, 256, S_FF>>>(
        fT1, fT1 + P8, wf + OFF_ra2W2, ra2_b2,
        fX, fX + P8, nullptr, nullptr, nullptr,
        outp, nullptr, nullptr, E);
}

// round 9
// speedup vs baseline: 2.0300x; 1.0086x over previous
#include <cuda_runtime.h>
#include <cuda_bf16.h>
#include <cstdint>

// ---------------- problem constants (fixed for this dataset) ----------------
#define D_    128
#define DA_   64
#define DB_   8
#define NR_   6
#define NS_   42
#define E_MAX 200000
#define T_MAX 1600000
#define RT_MAX 12504            // row-tiles of 16 covering grid*128 rows

// ---------------- scratch (static device globals; no allocation) ------------
__device__ __align__(16) uint4 g_fT1 [(size_t)2 * RT_MAX * 8 * 32];
__device__ __align__(16) uint4 g_fM  [(size_t)2 * RT_MAX * 8 * 32];
__device__ __align__(16) uint4 g_fX  [(size_t)2 * RT_MAX * 8 * 32];
__device__ __align__(16) uint4 g_fMin[(size_t)2 * RT_MAX * 8 * 32];
__device__ __align__(16) uint4 g_fAgg[(size_t)2 * RT_MAX * 4 * 32];
__device__ __align__(16) float g_down[(size_t)E_MAX * DA_];
__device__ __align__(16) float g_agg [(size_t)E_MAX * DA_];
__device__ __align__(16) float g_hrbf[(size_t)E_MAX * DB_];
__device__ __align__(16) float g_hsbf[(size_t)T_MAX * DB_];
__device__ __align__(16) uint32_t g_wfrag[163840];

#define OFF_Wkj    0
#define OFF_Wji    16384
#define OFF_rb1W1  32768
#define OFF_rb1W2  49152
#define OFF_Wfin   65536
#define OFF_ra1W1  81920
#define OFF_ra1W2  98304
#define OFF_ra2W1  114688
#define OFF_ra2W2  131072
#define OFF_Wdown  147456
#define OFF_Wup    155648

// ---------------- helpers ----------------------------------------------------
__device__ __forceinline__ float silu_f(float x) {
    return x / (1.0f + __expf(-x));
}
__device__ __forceinline__ void splitpack2(float x0, float x1,
                                           uint32_t& hi, uint32_t& lo) {
    asm("cvt.rn.bf16x2.f32 %0, %1, %2;" : "=r"(hi) : "f"(x1), "f"(x0));
    float f0 = __uint_as_float(hi << 16);
    float f1 = __uint_as_float(hi & 0xFFFF0000u);
    float l0 = x0 - f0;
    float l1 = x1 - f1;
    asm("cvt.rn.bf16x2.f32 %0, %1, %2;" : "=r"(lo) : "f"(l1), "f"(l0));
}
__device__ __forceinline__ float lo16f(uint32_t u) { return __uint_as_float(u << 16); }
__device__ __forceinline__ float hi16f(uint32_t u) { return __uint_as_float(u & 0xFFFF0000u); }

__device__ __forceinline__ void mma_bf16(float* c, const uint32_t* a, const uint32_t* b) {
    asm volatile(
        "mma.sync.aligned.m16n8k16.row.col.f32.bf16.bf16.f32 "
        "{%0,%1,%2,%3}, {%4,%5,%6,%7}, {%8,%9}, {%0,%1,%2,%3};"
        : "+f"(c[0]), "+f"(c[1]), "+f"(c[2]), "+f"(c[3])
        : "r"(a[0]), "r"(a[1]), "r"(a[2]), "r"(a[3]), "r"(b[0]), "r"(b[1]));
}
__device__ __forceinline__ void cp_async16(uint32_t saddr, const void* gaddr) {
    asm volatile("cp.async.cg.shared.global [%0], [%1], 16;"
                 :: "r"(saddr), "l"(gaddr));
}
#define CP_COMMIT() asm volatile("cp.async.commit_group;" ::: "memory")
#define CP_WAIT(n)  asm volatile("cp.async.wait_group %0;" :: "n"(n) : "memory")
__device__ __forceinline__ uint32_t smem_u32(const void* p) {
    uint32_t a;
    asm("{ .reg .u64 t; cvta.to.shared.u64 t, %1; cvt.u32.u64 %0, t; }" : "=r"(a) : "l"(p));
    return a;
}

// ---------------- epilogue modes ---------------------------------------------
#define EP_SILU        0
#define EP_SILU_ADDFR  1
#define EP_SILU_ADDF32 2
#define EP_SILU_MULRBF 3

// ---------------- tensor-core GEMM (validated R8) ------------------------------
template <int KT, int NT, int MODE, bool OUTF>
__global__ void __launch_bounds__(256, 2) gemm_mma(
    const uint4* __restrict__ Ah, const uint4* __restrict__ Al,
    const uint32_t* __restrict__ wfrag,
    const float* __restrict__ bias,
    const uint4* __restrict__ resH, const uint4* __restrict__ resL,
    const float* __restrict__ resF,
    const float* __restrict__ hrbf, const float* __restrict__ wrbf2,
    float* __restrict__ outF, uint4* __restrict__ outH, uint4* __restrict__ outL,
    int E)
{
    constexpr int NKS = KT;
    constexpr int NTN = NT / 8;
    constexpr int NWN = NT / 32;
    constexpr int SM_B = 4608;
    constexpr int B_BYTES = KT * NT * 64;
    constexpr int SM_A = SM_B + B_BYTES;

    extern __shared__ char smem[];
    const uint32_t sb = smem_u32(smem);
    float* sBias = (float*)smem;
    float* sW2   = (float*)(smem + 512);

    const int tid  = threadIdx.x;
    const int lane = tid & 31;
    const int wid  = tid >> 5;
    const int warpM = wid >> 2;
    const int warpN = wid & 3;
    const int rt0 = blockIdx.x * 8;

    {
        constexpr int CNT4 = B_BYTES / 16;
        const uint4* src = (const uint4*)wfrag;
#pragma unroll
        for (int i = 0; i < CNT4 / 256; i++) {
            int f = tid + i * 256;
            cp_async16(sb + SM_B + f * 16, src + f);
        }
    }
    auto prefA = [&](int s, int buf) {
#pragma unroll
        for (int i = 0; i < 2; i++) {
            int f   = tid + i * 256;
            int pl  = f >> 8;
            int rtl = (f >> 5) & 7;
            int ln  = f & 31;
            const uint4* src = (pl ? Al : Ah) + ((rt0 + rtl) * KT + s) * 32 + ln;
            cp_async16(sb + SM_A + buf * 8192 + f * 16, src);
        }
    };
    prefA(0, 0); CP_COMMIT();
    if (NKS > 1) { prefA(1, 1); CP_COMMIT(); }

    if (tid < NT) sBias[tid] = bias ? bias[tid] : 0.0f;
    if (MODE == EP_SILU_MULRBF)
        for (int i = tid; i < DB_ * NT; i += 256) sW2[i] = wrbf2[i];

    float acc[4][NWN][4];
#pragma unroll
    for (int mt = 0; mt < 4; mt++)
#pragma unroll
        for (int nt = 0; nt < NWN; nt++)
#pragma unroll
            for (int j = 0; j < 4; j++) acc[mt][nt][j] = 0.f;

#pragma unroll
    for (int s = 0; s < NKS; s++) {
        if (s + 2 < NKS) { prefA(s + 2, (s + 2) & 3); CP_COMMIT(); }
        if (s + 2 < NKS)      CP_WAIT(2);
        else if (s + 1 < NKS) CP_WAIT(1);
        else                  CP_WAIT(0);
        __syncthreads();

        const int buf = s & 3;
        const char* ab = smem + SM_A + buf * 8192;
        uint4 ahi[4], alo[4];
#pragma unroll
        for (int mt = 0; mt < 4; mt++) {
            int gm = warpM * 4 + mt;
            ahi[mt] = *(const uint4*)(ab + (gm * 32 + lane) * 16);
            alo[mt] = *(const uint4*)(ab + ((8 + gm) * 32 + lane) * 16);
        }
#pragma unroll
        for (int nt = 0; nt < NWN; nt++) {
            int gt = warpN * NWN + nt;
            uint4 bq = *(const uint4*)(smem + SM_B + (((s * NTN) + gt) * 32 + lane) * 16);
            uint32_t bh[2] = {bq.x, bq.y};
            uint32_t bl[2] = {bq.z, bq.w};
#pragma unroll
            for (int mt = 0; mt < 4; mt++) {
                mma_bf16(acc[mt][nt], (const uint32_t*)&ahi[mt], bh);
                mma_bf16(acc[mt][nt], (const uint32_t*)&ahi[mt], bl);
                mma_bf16(acc[mt][nt], (const uint32_t*)&alo[mt], bh);
            }
        }
    }

#pragma unroll
    for (int mt = 0; mt < 4; mt++) {
        const int rtg = rt0 + warpM * 4 + mt;
        if (rtg * 16 >= E) continue;

        float o[NWN][4];
#pragma unroll
        for (int nt = 0; nt < NWN; nt++) {
            int col = warpN * NWN * 8 + nt * 8 + 2 * (lane & 3);
#pragma unroll
            for (int half = 0; half < 2; half++) {
                o[nt][half * 2 + 0] = silu_f(acc[mt][nt][half * 2 + 0] + sBias[col]);
                o[nt][half * 2 + 1] = silu_f(acc[mt][nt][half * 2 + 1] + sBias[col + 1]);
            }
        }
        if (MODE == EP_SILU_MULRBF) {
            int rlo = rtg * 16 + (lane >> 2);
            float4 a0 = __ldg((const float4*)(hrbf + (size_t)rlo * DB_));
            float4 a1 = __ldg((const float4*)(hrbf + (size_t)rlo * DB_ + 4));
            float4 b0 = __ldg((const float4*)(hrbf + (size_t)(rlo + 8) * DB_));
            float4 b1 = __ldg((const float4*)(hrbf + (size_t)(rlo + 8) * DB_ + 4));
            float hA[8] = {a0.x, a0.y, a0.z, a0.w, a1.x, a1.y, a1.z, a1.w};
            float hB[8] = {b0.x, b0.y, b0.z, b0.w, b1.x, b1.y, b1.z, b1.w};
#pragma unroll
            for (int nt = 0; nt < NWN; nt++) {
                int col = warpN * NWN * 8 + nt * 8 + 2 * (lane & 3);
                float r0 = 0.f, r1 = 0.f, r2 = 0.f, r3 = 0.f;
#pragma unroll
                for (int j = 0; j < DB_; j++) {
                    float w0 = sW2[j * NT + col], w1 = sW2[j * NT + col + 1];
                    r0 += hA[j] * w0; r1 += hA[j] * w1;
                    r2 += hB[j] * w0; r3 += hB[j] * w1;
                }
                o[nt][0] *= r0; o[nt][1] *= r1; o[nt][2] *= r2; o[nt][3] *= r3;
            }
        } else if (MODE == EP_SILU_ADDF32) {
#pragma unroll
            for (int nt = 0; nt < NWN; nt++) {
                int col = warpN * NWN * 8 + nt * 8 + 2 * (lane & 3);
#pragma unroll
                for (int half = 0; half < 2; half++) {
                    int row = rtg * 16 + (lane >> 2) + half * 8;
                    float2 rr = __ldg((const float2*)(resF + (size_t)row * NT + col));
                    o[nt][half * 2 + 0] += rr.x;
                    o[nt][half * 2 + 1] += rr.y;
                }
            }
        } else if (MODE == EP_SILU_ADDFR) {
#pragma unroll
            for (int j = 0; j < NWN / 2; j++) {
                int q = ((rtg * (NT / 16)) + warpN * (NWN / 2) + j) * 32 + lane;
                uint4 rh = __ldg(resH + q);
                uint4 rl = __ldg(resL + q);
                o[2 * j    ][0] += lo16f(rh.x) + lo16f(rl.x);
                o[2 * j    ][1] += hi16f(rh.x) + hi16f(rl.x);
                o[2 * j    ][2] += lo16f(rh.y) + lo16f(rl.y);
                o[2 * j    ][3] += hi16f(rh.y) + hi16f(rl.y);
                o[2 * j + 1][0] += lo16f(rh.z) + lo16f(rl.z);
                o[2 * j + 1][1] += hi16f(rh.z) + hi16f(rl.z);
                o[2 * j + 1][2] += lo16f(rh.w) + lo16f(rl.w);
                o[2 * j + 1][3] += hi16f(rh.w) + hi16f(rl.w);
            }
        }

        if (OUTF) {
#pragma unroll
            for (int j = 0; j < NWN / 2; j++) {
                uint4 h, l;
                splitpack2(o[2 * j][0],     o[2 * j][1],     h.x, l.x);
                splitpack2(o[2 * j][2],     o[2 * j][3],     h.y, l.y);
                splitpack2(o[2 * j + 1][0], o[2 * j + 1][1], h.z, l.z);
                splitpack2(o[2 * j + 1][2], o[2 * j + 1][3], h.w, l.w);
                int q = ((rtg * (NT / 16)) + warpN * (NWN / 2) + j) * 32 + lane;
                outH[q] = h;
                outL[q] = l;
            }
        } else {
#pragma unroll
            for (int nt = 0; nt < NWN; nt++) {
                int col = warpN * NWN * 8 + nt * 8 + 2 * (lane & 3);
#pragma unroll
                for (int half = 0; half < 2; half++) {
                    int row = rtg * 16 + (lane >> 2) + half * 8;
                    if (row < E)
                        *(float2*)(outF + (size_t)row * NT + col) =
                            make_float2(o[nt][half * 2], o[nt][half * 2 + 1]);
                }
            }
        }
    }
}

// ---------------- activation split: fp32 rows -> fragment hi/lo planes --------
__global__ void __launch_bounds__(256) k_asplit(
    const float* __restrict__ src, int E, int KT,
    uint4* __restrict__ hi, uint4* __restrict__ lo)
{
    int idx = blockIdx.x * 256 + threadIdx.x;
    int RT = E / 16;
    if (idx >= RT * KT * 32) return;
    int lane = idx & 31;
    int s    = (idx >> 5) % KT;
    int rt   = idx / (32 * KT);
    int cols = KT * 16;
    int r0 = rt * 16 + (lane >> 2);
    int k0 = s * 16 + 2 * (lane & 3);
    const float* b0 = src + (size_t)r0 * cols + k0;
    const float* b1 = b0 + (size_t)8 * cols;
    float2 v0 = *(const float2*)(b0);
    float2 v1 = *(const float2*)(b1);
    float2 v2 = *(const float2*)(b0 + 8);
    float2 v3 = *(const float2*)(b1 + 8);
    uint4 h, l;
    splitpack2(v0.x, v0.y, h.x, l.x);
    splitpack2(v1.x, v1.y, h.y, l.y);
    splitpack2(v2.x, v2.y, h.z, l.z);
    splitpack2(v3.x, v3.y, h.w, l.w);
    hi[idx] = h;
    lo[idx] = l;
}

// ---------------- merged weight fragment prep ---------------------------------
__global__ void __launch_bounds__(256) k_wfrag_all(
    const float* w0, const float* w1, const float* w2, const float* w3,
    const float* w4, const float* w5, const float* w6, const float* w7,
    const float* w8, const float* w9, const float* w10,
    uint32_t* __restrict__ outv)
{
    const float* Ws[11] = {w0, w1, w2, w3, w4, w5, w6, w7, w8, w9, w10};
    int b = blockIdx.x;
    const float* W;
    int K, N, off, lidx;
    if (b < 144) {
        int w = b / 16;
        W = Ws[w]; K = 128; N = 128;
        off = w * 16384;
        lidx = (b % 16) * 256 + threadIdx.x;
    } else if (b < 152) {
        W = Ws[9]; K = 128; N = 64; off = OFF_Wdown;
        lidx = (b - 144) * 256 + threadIdx.x;
    } else {
        W = Ws[10]; K = 64; N = 128; off = OFF_Wup;
        lidx = (b - 152) * 256 + threadIdx.x;
    }
    int total = (K / 16) * (N / 8) * 32;
    if (lidx >= total) return;
    int lane = lidx & 31;
    int st   = lidx >> 5;
    int t    = st % (N / 8);
    int s    = st / (N / 8);
    int q = lane & 3, r = lane >> 2;
    int n  = t * 8 + r;
    int k0 = s * 16 + 2 * q;
    float a00 = __ldg(W + (size_t)k0 * N + n);
    float a01 = __ldg(W + (size_t)(k0 + 1) * N + n);
    float a10 = __ldg(W + (size_t)(k0 + 8) * N + n);
    float a11 = __ldg(W + (size_t)(k0 + 9) * N + n);
    uint32_t h0, l0, h1, l1;
    splitpack2(a00, a01, h0, l0);
    splitpack2(a10, a11, h1, l1);
    ((uint4*)(outv + off))[lidx] = make_uint4(h0, h1, l0, l1);
}

// ---------------- small kernels -------------------------------------------------
__global__ void __launch_bounds__(256) k_zero(float4* __restrict__ p, int n4) {
    int i = blockIdx.x * blockDim.x + threadIdx.x;
    if (i < n4) p[i] = make_float4(0.f, 0.f, 0.f, 0.f);
}

__global__ void __launch_bounds__(256) k_hrbf(
    const float* __restrict__ rbf, const float* __restrict__ w1,
    float* __restrict__ out, int E)
{
    __shared__ float sw[NR_ * DB_];
    if (threadIdx.x < NR_ * DB_) sw[threadIdx.x] = w1[threadIdx.x];
    __syncthreads();
    int r = blockIdx.x * blockDim.x + threadIdx.x;
    if (r >= E) return;
    float x[NR_];
#pragma unroll
    for (int j = 0; j < NR_; j++) x[j] = __ldg(rbf + (size_t)r * NR_ + j);
    float h[DB_];
#pragma unroll
    for (int k = 0; k < DB_; k++) h[k] = 0.f;
#pragma unroll
    for (int j = 0; j < NR_; j++)
#pragma unroll
        for (int k = 0; k < DB_; k++) h[k] += x[j] * sw[j * DB_ + k];
    float4* op = (float4*)(out + (size_t)r * DB_);
    op[0] = make_float4(h[0], h[1], h[2], h[3]);
    op[1] = make_float4(h[4], h[5], h[6], h[7]);
}

// h_sbf[T,8] = sbf[T,42] @ Wsbf1[42,8] — float4-vectorized streaming
__global__ void __launch_bounds__(256) k_hsbf(
    const float* __restrict__ sbf, const float* __restrict__ w1,
    float* __restrict__ out, int T)
{
    __shared__ float st[256 * NS_];
    __shared__ float sw[NS_ * DB_];
    for (int i = threadIdx.x; i < NS_ * DB_; i += 256) sw[i] = w1[i];

    int base = blockIdx.x * 256;
    int n = T - base; if (n > 256) n = 256;
    int total = n * NS_;
    int t4 = total >> 2;
    const float4* s4 = (const float4*)(sbf + (size_t)base * NS_);
    for (int i = threadIdx.x; i < t4; i += 256)
        ((float4*)st)[i] = __ldg(s4 + i);
    for (int i = t4 * 4 + threadIdx.x; i < total; i += 256)
        st[i] = sbf[(size_t)base * NS_ + i];
    __syncthreads();

    int r = threadIdx.x;
    if (r >= n) return;
    const float* x = &st[r * NS_];
    float h[DB_];
#pragma unroll
    for (int k = 0; k < DB_; k++) h[k] = 0.f;
#pragma unroll
    for (int j = 0; j < NS_; j++) {
        float xv = x[j];
#pragma unroll
        for (int k = 0; k < DB_; k++) h[k] += xv * sw[j * DB_ + k];
    }
    float4* op = (float4*)(out + (size_t)(base + r) * DB_);
    op[0] = make_float4(h[0], h[1], h[2], h[3]);
    op[1] = make_float4(h[4], h[5], h[6], h[7]);
}

__global__ void __launch_bounds__(256) k_triplet(
    const float* __restrict__ hsbf, const float* __restrict__ wsbf2,
    const int* __restrict__ exp_kj, const int* __restrict__ red_ji,
    const float* __restrict__ down, float* __restrict__ agg, int T)
{
    __shared__ float sw[DB_ * DA_];
    for (int i = threadIdx.x; i < DB_ * DA_; i += 256) sw[i] = wsbf2[i];
    __syncthreads();

    const int q = threadIdx.x & 15;
    float w[DB_][4];
#pragma unroll
    for (int i = 0; i < DB_; i++)
#pragma unroll
        for (int j = 0; j < 4; j++) w[i][j] = sw[i * DA_ + q * 4 + j];

    int t = (blockIdx.x * blockDim.x + threadIdx.x) >> 4;
    const int stride = (gridDim.x * blockDim.x) >> 4;

    for (; t < T; t += stride) {
        int e = __ldg(exp_kj + t);
        int g = __ldg(red_ji + t);
        const float4* hp = (const float4*)(hsbf + (size_t)t * DB_);
        float4 h0 = __ldg(hp), h1 = __ldg(hp + 1);
        float hh[8] = {h0.x, h0.y, h0.z, h0.w, h1.x, h1.y, h1.z, h1.w};

        float s0 = 0.f, s1 = 0.f, s2 = 0.f, s3 = 0.f;
#pragma unroll
        for (int i = 0; i < DB_; i++) {
            s0 += hh[i] * w[i][0];
            s1 += hh[i] * w[i][1];
            s2 += hh[i] * w[i][2];
            s3 += hh[i] * w[i][3];
        }
        float4 a = __ldg((const float4*)(down + (size_t)e * DA_ + q * 4));
        float vx = a.x * s0, vy = a.y * s1, vz = a.z * s2, vw = a.w * s3;

        float* dst = agg + (size_t)g * DA_ + q * 4;
        asm volatile("red.global.add.v4.f32 [%0], {%1, %2, %3, %4};"
                     :: "l"(dst), "f"(vx), "f"(vy), "f"(vz), "f"(vw)
                     : "memory");
    }
}

// ---------------- launch -------------------------------------------------------
static inline int smem_sz(int KT, int NT) { return 4608 + KT * NT * 64 + 32768; }

extern "C" void kernel_launch(void* const* d_in, const int* in_sizes, int n_in,
                              void* d_out, int out_size)
{
    const float* m_input  = (const float*)d_in[0];
    const float* rbf      = (const float*)d_in[1];
    const float* sbf      = (const float*)d_in[2];
    const float* Wkj      = (const float*)d_in[3];
    const float* bkj      = (const float*)d_in[4];
    const float* Wrbf1    = (const float*)d_in[5];
    const float* Wrbf2    = (const float*)d_in[6];
    const float* Wdown    = (const float*)d_in[7];
    const float* Wsbf1    = (const float*)d_in[8];
    const float* Wsbf2    = (const float*)d_in[9];
    const float* Wup      = (const float*)d_in[10];
    const float* Wji      = (const float*)d_in[11];
    const float* bji      = (const float*)d_in[12];
    const float* rb1_W1   = (const float*)d_in[13];
    const float* rb1_b1   = (const float*)d_in[14];
    const float* rb1_W2   = (const float*)d_in[15];
    const float* rb1_b2   = (const float*)d_in[16];
    const float* Wfin     = (const float*)d_in[17];
    const float* bfin     = (const float*)d_in[18];
    const float* ra1_W1   = (const float*)d_in[19];
    const float* ra1_b1   = (const float*)d_in[20];
    const float* ra1_W2   = (const float*)d_in[21];
    const float* ra1_b2   = (const float*)d_in[22];
    const float* ra2_W1   = (const float*)d_in[23];
    const float* ra2_b1   = (const float*)d_in[24];
    const float* ra2_W2   = (const float*)d_in[25];
    const float* ra2_b2   = (const float*)d_in[26];
    const int*   red_ji   = (const int*)  d_in[27];
    const int*   exp_kj   = (const int*)  d_in[28];

    const int E = in_sizes[0] / D_;
    const int T = in_sizes[27];

    uint4 *fT1, *fM, *fX, *fMin, *fAgg;
    float *down, *agg, *hrbf, *hsbf;
    uint32_t *wf;
    cudaGetSymbolAddress((void**)&fT1,  g_fT1);
    cudaGetSymbolAddress((void**)&fM,   g_fM);
    cudaGetSymbolAddress((void**)&fX,   g_fX);
    cudaGetSymbolAddress((void**)&fMin, g_fMin);
    cudaGetSymbolAddress((void**)&fAgg, g_fAgg);
    cudaGetSymbolAddress((void**)&down, g_down);
    cudaGetSymbolAddress((void**)&agg,  g_agg);
    cudaGetSymbolAddress((void**)&hrbf, g_hrbf);
    cudaGetSymbolAddress((void**)&hsbf, g_hsbf);
    cudaGetSymbolAddress((void**)&wf,   g_wfrag);

    const size_t P8 = (size_t)RT_MAX * 8 * 32;
    const size_t P4 = (size_t)RT_MAX * 4 * 32;

    float* outp = (float*)d_out;
    const int grid = (E + 127) / 128;

    const int S_FF = smem_sz(8, 128);
    const int S_FD = smem_sz(8, 64);
    const int S_DF = smem_sz(4, 128);
    cudaFuncSetAttribute((const void*)gemm_mma<8,128,EP_SILU,true>,        cudaFuncAttributeMaxDynamicSharedMemorySize, S_FF);
    cudaFuncSetAttribute((const void*)gemm_mma<8,128,EP_SILU_ADDFR,true>,  cudaFuncAttributeMaxDynamicSharedMemorySize, S_FF);
    cudaFuncSetAttribute((const void*)gemm_mma<8,128,EP_SILU_ADDFR,false>, cudaFuncAttributeMaxDynamicSharedMemorySize, S_FF);
    cudaFuncSetAttribute((const void*)gemm_mma<8,128,EP_SILU_ADDF32,true>, cudaFuncAttributeMaxDynamicSharedMemorySize, S_FF);
    cudaFuncSetAttribute((const void*)gemm_mma<8,128,EP_SILU_MULRBF,true>, cudaFuncAttributeMaxDynamicSharedMemorySize, S_FF);
    cudaFuncSetAttribute((const void*)gemm_mma<8,64, EP_SILU,false>,       cudaFuncAttributeMaxDynamicSharedMemorySize, S_FD);
    cudaFuncSetAttribute((const void*)gemm_mma<4,128,EP_SILU,true>,        cudaFuncAttributeMaxDynamicSharedMemorySize, S_DF);

    // ---- side stream for memory-bound prep (overlaps tensor-bound GEMMs) ----
    cudaStream_t s2;
    cudaStreamCreateWithFlags(&s2, cudaStreamNonBlocking);
    cudaEvent_t evFork, evJoin;
    cudaEventCreateWithFlags(&evFork, cudaEventDisableTiming);
    cudaEventCreateWithFlags(&evJoin, cudaEventDisableTiming);

    // fork: s2 runs {zero(agg), hsbf} concurrently with main-stream prep+GEMMs
    cudaEventRecord(evFork, 0);
    cudaStreamWaitEvent(s2, evFork, 0);
    {
        int n4 = (E * DA_) / 4;
        k_zero<<<(n4 + 255) / 256, 256, 0, s2>>>((float4*)agg, n4);
    }
    k_hsbf<<<(T + 255) / 256, 256, 0, s2>>>(sbf, Wsbf1, hsbf, T);
    cudaEventRecord(evJoin, s2);

    // main stream: prep for the Wkj chain
    k_wfrag_all<<<160, 256>>>(Wkj, Wji, rb1_W1, rb1_W2, Wfin,
                              ra1_W1, ra1_W2, ra2_W1, ra2_W2, Wdown, Wup, wf);
    k_hrbf<<<(E + 255) / 256, 256>>>(rbf, Wrbf1, hrbf, E);
    {
        int nq = (E / 16) * 8 * 32;
        k_asplit<<<(nq + 255) / 256, 256>>>(m_input, E, 8, fMin, fMin + P8);
    }

    // 4. t1 = silu(m_input @ Wkj + bkj) * rbfmod
    gemm_mma<8,128,EP_SILU_MULRBF,true><<<grid, 256, S_FF>>>(
        fMin, fMin + P8, wf + OFF_Wkj, bkj,
        nullptr, nullptr, nullptr, hrbf, Wrbf2,
        nullptr, fT1, fT1 + P8, E);
    // 5. down = silu(t1 @ Wdown)
    gemm_mma<8,64,EP_SILU,false><<<grid, 256, S_FD>>>(
        fT1, fT1 + P8, wf + OFF_Wdown, nullptr,
        nullptr, nullptr, nullptr, nullptr, nullptr,
        down, nullptr, nullptr, E);

    // join: triplet needs hsbf + zeroed agg
    cudaStreamWaitEvent(0, evJoin, 0);

    // 6. triplet -> agg, split
    k_triplet<<<2048, 256>>>(hsbf, Wsbf2, exp_kj, red_ji, down, agg, T);
    {
        int nq = (E / 16) * 4 * 32;
        k_asplit<<<(nq + 255) / 256, 256>>>(agg, E, 4, fAgg, fAgg + P4);
    }
    // 7. prop = silu(agg @ Wup) -> fT1
    gemm_mma<4,128,EP_SILU,true><<<grid, 256, S_DF>>>(
        fAgg, fAgg + P4, wf + OFF_Wup, nullptr,
        nullptr, nullptr, nullptr, nullptr, nullptr,
        nullptr, fT1, fT1 + P8, E);
    // 8. m = silu(m_input @ Wji + bji) + prop -> fM
    gemm_mma<8,128,EP_SILU_ADDFR,true><<<grid, 256, S_FF>>>(
        fMin, fMin + P8, wf + OFF_Wji, bji,
        fT1, fT1 + P8, nullptr, nullptr, nullptr,
        nullptr, fM, fM + P8, E);
    // 9-10. residual block b1: fM -> fX
    gemm_mma<8,128,EP_SILU,true><<<grid, 256, S_FF>>>(
        fM, fM + P8, wf + OFF_rb1W1, rb1_b1,
        nullptr, nullptr, nullptr, nullptr, nullptr,
        nullptr, fT1, fT1 + P8, E);
    gemm_mma<8,128,EP_SILU_ADDFR,true><<<grid, 256, S_FF>>>(
        fT1, fT1 + P8, wf + OFF_rb1W2, rb1_b2,
        fM, fM + P8, nullptr, nullptr, nullptr,
        nullptr, fX, fX + P8, E);
    // 11. m = silu(fX @ Wfin + bfin) + m_input -> fM
    gemm_mma<8,128,EP_SILU_ADDF32,true><<<grid, 256, S_FF>>>(
        fX, fX + P8, wf + OFF_Wfin, bfin,
        nullptr, nullptr, m_input, nullptr, nullptr,
        nullptr, fM, fM + P8, E);
    // 12-13. residual block a1: fM -> fX
    gemm_mma<8,128,EP_SILU,true><<<grid, 256, S_FF>>>(
        fM, fM + P8, wf + OFF_ra1W1, ra1_b1,
        nullptr, nullptr, nullptr, nullptr, nullptr,
        nullptr, fT1, fT1 + P8, E);
    gemm_mma<8,128,EP_SILU_ADDFR,true><<<grid, 256, S_FF>>>(
        fT1, fT1 + P8, wf + OFF_ra1W2, ra1_b2,
        fM, fM + P8, nullptr, nullptr, nullptr,
        nullptr, fX, fX + P8, E);
    // 14-15. residual block a2: fX -> d_out
    gemm_mma<8,128,EP_SILU,true><<<grid, 256, S_FF>>>(
        fX, fX + P8, wf + OFF_ra2W1, ra2_b1,
        nullptr, nullptr, nullptr, nullptr, nullptr,
        nullptr, fT1, fT1 + P8, E);
    gemm_mma<8,128,EP_SILU_ADDFR,false><<<grid, 256, S_FF>>>(
        fT1, fT1 + P8, wf + OFF_ra2W2, ra2_b2,
        fX, fX + P8, nullptr, nullptr, nullptr,
        outp, nullptr, nullptr, E);

    cudaEventDestroy(evFork);
    cudaEventDestroy(evJoin);
    cudaStreamDestroy(s2);
}

// round 10
// speedup vs baseline: 2.0492x; 1.0095x over previous
#include <cuda_runtime.h>
#include <cuda_bf16.h>
#include <cstdint>

// ---------------- problem constants (fixed for this dataset) ----------------
#define D_    128
#define DA_   64
#define DB_   8
#define NR_   6
#define NS_   42
#define E_MAX 200000
#define T_MAX 1600000
#define RT_MAX 12504            // row-tiles of 16 covering grid*128 rows

// ---------------- scratch (static device globals; no allocation) ------------
__device__ __align__(16) uint4 g_fT1 [(size_t)2 * RT_MAX * 8 * 32];
__device__ __align__(16) uint4 g_fM  [(size_t)2 * RT_MAX * 8 * 32];
__device__ __align__(16) uint4 g_fX  [(size_t)2 * RT_MAX * 8 * 32];
__device__ __align__(16) uint4 g_fMin[(size_t)2 * RT_MAX * 8 * 32];
__device__ __align__(16) uint4 g_fAgg[(size_t)2 * RT_MAX * 4 * 32];
__device__ __align__(16) float g_down[(size_t)E_MAX * DA_];
__device__ __align__(16) float g_agg [(size_t)E_MAX * DA_];
__device__ __align__(16) float g_wcomb[NR_ * D_];          // Wrbf1 @ Wrbf2 (6x128)
__device__ __align__(16) float g_hsbf[(size_t)T_MAX * DB_];
__device__ __align__(16) uint32_t g_wfrag[163840];

#define OFF_Wkj    0
#define OFF_Wji    16384
#define OFF_rb1W1  32768
#define OFF_rb1W2  49152
#define OFF_Wfin   65536
#define OFF_ra1W1  81920
#define OFF_ra1W2  98304
#define OFF_ra2W1  114688
#define OFF_ra2W2  131072
#define OFF_Wdown  147456
#define OFF_Wup    155648

// ---------------- helpers ----------------------------------------------------
__device__ __forceinline__ float silu_f(float x) {
    return x / (1.0f + __expf(-x));
}
__device__ __forceinline__ void splitpack2(float x0, float x1,
                                           uint32_t& hi, uint32_t& lo) {
    asm("cvt.rn.bf16x2.f32 %0, %1, %2;" : "=r"(hi) : "f"(x1), "f"(x0));
    float f0 = __uint_as_float(hi << 16);
    float f1 = __uint_as_float(hi & 0xFFFF0000u);
    float l0 = x0 - f0;
    float l1 = x1 - f1;
    asm("cvt.rn.bf16x2.f32 %0, %1, %2;" : "=r"(lo) : "f"(l1), "f"(l0));
}
__device__ __forceinline__ float lo16f(uint32_t u) { return __uint_as_float(u << 16); }
__device__ __forceinline__ float hi16f(uint32_t u) { return __uint_as_float(u & 0xFFFF0000u); }

__device__ __forceinline__ void mma_bf16(float* c, const uint32_t* a, const uint32_t* b) {
    asm volatile(
        "mma.sync.aligned.m16n8k16.row.col.f32.bf16.bf16.f32 "
        "{%0,%1,%2,%3}, {%4,%5,%6,%7}, {%8,%9}, {%0,%1,%2,%3};"
        : "+f"(c[0]), "+f"(c[1]), "+f"(c[2]), "+f"(c[3])
        : "r"(a[0]), "r"(a[1]), "r"(a[2]), "r"(a[3]), "r"(b[0]), "r"(b[1]));
}
__device__ __forceinline__ void cp_async16(uint32_t saddr, const void* gaddr) {
    asm volatile("cp.async.cg.shared.global [%0], [%1], 16;"
                 :: "r"(saddr), "l"(gaddr));
}
#define CP_COMMIT() asm volatile("cp.async.commit_group;" ::: "memory")
#define CP_WAIT(n)  asm volatile("cp.async.wait_group %0;" :: "n"(n) : "memory")
__device__ __forceinline__ uint32_t smem_u32(const void* p) {
    uint32_t a;
    asm("{ .reg .u64 t; cvta.to.shared.u64 t, %1; cvt.u32.u64 %0, t; }" : "=r"(a) : "l"(p));
    return a;
}

// ---------------- epilogue modes ---------------------------------------------
#define EP_SILU        0
#define EP_SILU_ADDFR  1
#define EP_SILU_ADDF32 2
#define EP_SILU_MULRBF 3   // * (rbf @ Wcomb), rbf 6/row

// ---------------- tensor-core GEMM (validated R8/R9 core) ----------------------
template <int KT, int NT, int MODE, bool OUTF>
__global__ void __launch_bounds__(256, 2) gemm_mma(
    const uint4* __restrict__ Ah, const uint4* __restrict__ Al,
    const uint32_t* __restrict__ wfrag,
    const float* __restrict__ bias,
    const uint4* __restrict__ resH, const uint4* __restrict__ resL,
    const float* __restrict__ resF,
    const float* __restrict__ rbf, const float* __restrict__ wcomb,
    float* __restrict__ outF, uint4* __restrict__ outH, uint4* __restrict__ outL,
    int E)
{
    constexpr int NKS = KT;
    constexpr int NTN = NT / 8;
    constexpr int NWN = NT / 32;
    constexpr int SM_B = 4608;
    constexpr int B_BYTES = KT * NT * 64;
    constexpr int SM_A = SM_B + B_BYTES;

    extern __shared__ char smem[];
    const uint32_t sb = smem_u32(smem);
    float* sBias = (float*)smem;
    float* sW2   = (float*)(smem + 512);     // Wcomb 6xNT when MULRBF

    const int tid  = threadIdx.x;
    const int lane = tid & 31;
    const int wid  = tid >> 5;
    const int warpM = wid >> 2;
    const int warpN = wid & 3;
    const int rt0 = blockIdx.x * 8;

    {
        constexpr int CNT4 = B_BYTES / 16;
        const uint4* src = (const uint4*)wfrag;
#pragma unroll
        for (int i = 0; i < CNT4 / 256; i++) {
            int f = tid + i * 256;
            cp_async16(sb + SM_B + f * 16, src + f);
        }
    }
    auto prefA = [&](int s, int buf) {
#pragma unroll
        for (int i = 0; i < 2; i++) {
            int f   = tid + i * 256;
            int pl  = f >> 8;
            int rtl = (f >> 5) & 7;
            int ln  = f & 31;
            const uint4* src = (pl ? Al : Ah) + ((rt0 + rtl) * KT + s) * 32 + ln;
            cp_async16(sb + SM_A + buf * 8192 + f * 16, src);
        }
    };
    prefA(0, 0); CP_COMMIT();
    if (NKS > 1) { prefA(1, 1); CP_COMMIT(); }

    if (tid < NT) sBias[tid] = bias ? bias[tid] : 0.0f;
    if (MODE == EP_SILU_MULRBF)
        for (int i = tid; i < NR_ * NT; i += 256) sW2[i] = wcomb[i];

    float acc[4][NWN][4];
#pragma unroll
    for (int mt = 0; mt < 4; mt++)
#pragma unroll
        for (int nt = 0; nt < NWN; nt++)
#pragma unroll
            for (int j = 0; j < 4; j++) acc[mt][nt][j] = 0.f;

#pragma unroll
    for (int s = 0; s < NKS; s++) {
        if (s + 2 < NKS) { prefA(s + 2, (s + 2) & 3); CP_COMMIT(); }
        if (s + 2 < NKS)      CP_WAIT(2);
        else if (s + 1 < NKS) CP_WAIT(1);
        else                  CP_WAIT(0);
        __syncthreads();

        const int buf = s & 3;
        const char* ab = smem + SM_A + buf * 8192;
        uint4 ahi[4], alo[4];
#pragma unroll
        for (int mt = 0; mt < 4; mt++) {
            int gm = warpM * 4 + mt;
            ahi[mt] = *(const uint4*)(ab + (gm * 32 + lane) * 16);
            alo[mt] = *(const uint4*)(ab + ((8 + gm) * 32 + lane) * 16);
        }
#pragma unroll
        for (int nt = 0; nt < NWN; nt++) {
            int gt = warpN * NWN + nt;
            uint4 bq = *(const uint4*)(smem + SM_B + (((s * NTN) + gt) * 32 + lane) * 16);
            uint32_t bh[2] = {bq.x, bq.y};
            uint32_t bl[2] = {bq.z, bq.w};
#pragma unroll
            for (int mt = 0; mt < 4; mt++) {
                mma_bf16(acc[mt][nt], (const uint32_t*)&ahi[mt], bh);
                mma_bf16(acc[mt][nt], (const uint32_t*)&ahi[mt], bl);
                mma_bf16(acc[mt][nt], (const uint32_t*)&alo[mt], bh);
            }
        }
    }

#pragma unroll
    for (int mt = 0; mt < 4; mt++) {
        const int rtg = rt0 + warpM * 4 + mt;
        if (rtg * 16 >= E) continue;

        float o[NWN][4];
#pragma unroll
        for (int nt = 0; nt < NWN; nt++) {
            int col = warpN * NWN * 8 + nt * 8 + 2 * (lane & 3);
#pragma unroll
            for (int half = 0; half < 2; half++) {
                o[nt][half * 2 + 0] = silu_f(acc[mt][nt][half * 2 + 0] + sBias[col]);
                o[nt][half * 2 + 1] = silu_f(acc[mt][nt][half * 2 + 1] + sBias[col + 1]);
            }
        }
        if (MODE == EP_SILU_MULRBF) {
            int rA = rtg * 16 + (lane >> 2);
            int rB = rA + 8;
            if (rA >= E) rA = E - 1;
            if (rB >= E) rB = E - 1;
            const float* pa = rbf + (size_t)rA * NR_;
            const float* pb = rbf + (size_t)rB * NR_;
            float2 a0 = __ldg((const float2*)pa), a1 = __ldg((const float2*)pa + 1),
                   a2 = __ldg((const float2*)pa + 2);
            float2 b0 = __ldg((const float2*)pb), b1 = __ldg((const float2*)pb + 1),
                   b2 = __ldg((const float2*)pb + 2);
            float hA[6] = {a0.x, a0.y, a1.x, a1.y, a2.x, a2.y};
            float hB[6] = {b0.x, b0.y, b1.x, b1.y, b2.x, b2.y};
#pragma unroll
            for (int nt = 0; nt < NWN; nt++) {
                int col = warpN * NWN * 8 + nt * 8 + 2 * (lane & 3);
                float r0 = 0.f, r1 = 0.f, r2 = 0.f, r3 = 0.f;
#pragma unroll
                for (int j = 0; j < NR_; j++) {
                    float w0 = sW2[j * NT + col], w1 = sW2[j * NT + col + 1];
                    r0 += hA[j] * w0; r1 += hA[j] * w1;
                    r2 += hB[j] * w0; r3 += hB[j] * w1;
                }
                o[nt][0] *= r0; o[nt][1] *= r1; o[nt][2] *= r2; o[nt][3] *= r3;
            }
        } else if (MODE == EP_SILU_ADDF32) {
#pragma unroll
            for (int nt = 0; nt < NWN; nt++) {
                int col = warpN * NWN * 8 + nt * 8 + 2 * (lane & 3);
#pragma unroll
                for (int half = 0; half < 2; half++) {
                    int row = rtg * 16 + (lane >> 2) + half * 8;
                    if (row >= E) row = E - 1;
                    float2 rr = __ldg((const float2*)(resF + (size_t)row * NT + col));
                    o[nt][half * 2 + 0] += rr.x;
                    o[nt][half * 2 + 1] += rr.y;
                }
            }
        } else if (MODE == EP_SILU_ADDFR) {
#pragma unroll
            for (int j = 0; j < NWN / 2; j++) {
                int q = ((rtg * (NT / 16)) + warpN * (NWN / 2) + j) * 32 + lane;
                uint4 rh = __ldg(resH + q);
                uint4 rl = __ldg(resL + q);
                o[2 * j    ][0] += lo16f(rh.x) + lo16f(rl.x);
                o[2 * j    ][1] += hi16f(rh.x) + hi16f(rl.x);
                o[2 * j    ][2] += lo16f(rh.y) + lo16f(rl.y);
                o[2 * j    ][3] += hi16f(rh.y) + hi16f(rl.y);
                o[2 * j + 1][0] += lo16f(rh.z) + lo16f(rl.z);
                o[2 * j + 1][1] += hi16f(rh.z) + hi16f(rl.z);
                o[2 * j + 1][2] += lo16f(rh.w) + lo16f(rl.w);
                o[2 * j + 1][3] += hi16f(rh.w) + hi16f(rl.w);
            }
        }

        if (OUTF) {
#pragma unroll
            for (int j = 0; j < NWN / 2; j++) {
                uint4 h, l;
                splitpack2(o[2 * j][0],     o[2 * j][1],     h.x, l.x);
                splitpack2(o[2 * j][2],     o[2 * j][3],     h.y, l.y);
                splitpack2(o[2 * j + 1][0], o[2 * j + 1][1], h.z, l.z);
                splitpack2(o[2 * j + 1][2], o[2 * j + 1][3], h.w, l.w);
                int q = ((rtg * (NT / 16)) + warpN * (NWN / 2) + j) * 32 + lane;
                outH[q] = h;
                outL[q] = l;
            }
        } else {
#pragma unroll
            for (int nt = 0; nt < NWN; nt++) {
                int col = warpN * NWN * 8 + nt * 8 + 2 * (lane & 3);
#pragma unroll
                for (int half = 0; half < 2; half++) {
                    int row = rtg * 16 + (lane >> 2) + half * 8;
                    if (row < E)
                        *(float2*)(outF + (size_t)row * NT + col) =
                            make_float2(o[nt][half * 2], o[nt][half * 2 + 1]);
                }
            }
        }
    }
}

// ---------------- activation split: fp32 rows -> fragment hi/lo planes --------
__global__ void __launch_bounds__(256) k_asplit(
    const float* __restrict__ src, int E, int KT,
    uint4* __restrict__ hi, uint4* __restrict__ lo)
{
    int idx = blockIdx.x * 256 + threadIdx.x;
    int RT = E / 16;
    if (idx >= RT * KT * 32) return;
    int lane = idx & 31;
    int s    = (idx >> 5) % KT;
    int rt   = idx / (32 * KT);
    int cols = KT * 16;
    int r0 = rt * 16 + (lane >> 2);
    int k0 = s * 16 + 2 * (lane & 3);
    const float* b0 = src + (size_t)r0 * cols + k0;
    const float* b1 = b0 + (size_t)8 * cols;
    float2 v0 = *(const float2*)(b0);
    float2 v1 = *(const float2*)(b1);
    float2 v2 = *(const float2*)(b0 + 8);
    float2 v3 = *(const float2*)(b1 + 8);
    uint4 h, l;
    splitpack2(v0.x, v0.y, h.x, l.x);
    splitpack2(v1.x, v1.y, h.y, l.y);
    splitpack2(v2.x, v2.y, h.z, l.z);
    splitpack2(v3.x, v3.y, h.w, l.w);
    hi[idx] = h;
    lo[idx] = l;
}

// ---------------- merged weight fragment prep ---------------------------------
__global__ void __launch_bounds__(256) k_wfrag_all(
    const float* w0, const float* w1, const float* w2, const float* w3,
    const float* w4, const float* w5, const float* w6, const float* w7,
    const float* w8, const float* w9, const float* w10,
    uint32_t* __restrict__ outv)
{
    const float* Ws[11] = {w0, w1, w2, w3, w4, w5, w6, w7, w8, w9, w10};
    int b = blockIdx.x;
    const float* W;
    int K, N, off, lidx;
    if (b < 144) {
        int w = b / 16;
        W = Ws[w]; K = 128; N = 128;
        off = w * 16384;
        lidx = (b % 16) * 256 + threadIdx.x;
    } else if (b < 152) {
        W = Ws[9]; K = 128; N = 64; off = OFF_Wdown;
        lidx = (b - 144) * 256 + threadIdx.x;
    } else {
        W = Ws[10]; K = 64; N = 128; off = OFF_Wup;
        lidx = (b - 152) * 256 + threadIdx.x;
    }
    int total = (K / 16) * (N / 8) * 32;
    if (lidx >= total) return;
    int lane = lidx & 31;
    int st   = lidx >> 5;
    int t    = st % (N / 8);
    int s    = st / (N / 8);
    int q = lane & 3, r = lane >> 2;
    int n  = t * 8 + r;
    int k0 = s * 16 + 2 * q;
    float a00 = __ldg(W + (size_t)k0 * N + n);
    float a01 = __ldg(W + (size_t)(k0 + 1) * N + n);
    float a10 = __ldg(W + (size_t)(k0 + 8) * N + n);
    float a11 = __ldg(W + (size_t)(k0 + 9) * N + n);
    uint32_t h0, l0, h1, l1;
    splitpack2(a00, a01, h0, l0);
    splitpack2(a10, a11, h1, l1);
    ((uint4*)(outv + off))[lidx] = make_uint4(h0, h1, l0, l1);
}

// ---------------- Wcomb = Wrbf1[6,8] @ Wrbf2[8,128] ----------------------------
__global__ void __launch_bounds__(256) k_wcomb(
    const float* __restrict__ w1, const float* __restrict__ w2,
    float* __restrict__ out)
{
    int idx = blockIdx.x * 256 + threadIdx.x;
    if (idx >= NR_ * D_) return;
    int j = idx / D_, n = idx % D_;
    float s = 0.f;
#pragma unroll
    for (int k = 0; k < DB_; k++) s += w1[j * DB_ + k] * w2[k * D_ + n];
    out[idx] = s;
}

// ---------------- small kernels -------------------------------------------------
__global__ void __launch_bounds__(256) k_zero(float4* __restrict__ p, int n4) {
    int i = blockIdx.x * blockDim.x + threadIdx.x;
    if (i < n4) p[i] = make_float4(0.f, 0.f, 0.f, 0.f);
}

// h_sbf[T,8] = sbf[T,42] @ Wsbf1[42,8] — float4-vectorized streaming
__global__ void __launch_bounds__(256) k_hsbf(
    const float* __restrict__ sbf, const float* __restrict__ w1,
    float* __restrict__ out, int T)
{
    __shared__ float st[256 * NS_];
    __shared__ float sw[NS_ * DB_];
    for (int i = threadIdx.x; i < NS_ * DB_; i += 256) sw[i] = w1[i];

    int base = blockIdx.x * 256;
    int n = T - base; if (n > 256) n = 256;
    int total = n * NS_;
    int t4 = total >> 2;
    const float4* s4 = (const float4*)(sbf + (size_t)base * NS_);
    for (int i = threadIdx.x; i < t4; i += 256)
        ((float4*)st)[i] = __ldg(s4 + i);
    for (int i = t4 * 4 + threadIdx.x; i < total; i += 256)
        st[i] = sbf[(size_t)base * NS_ + i];
    __syncthreads();

    int r = threadIdx.x;
    if (r >= n) return;
    const float* x = &st[r * NS_];
    float h[DB_];
#pragma unroll
    for (int k = 0; k < DB_; k++) h[k] = 0.f;
#pragma unroll
    for (int j = 0; j < NS_; j++) {
        float xv = x[j];
#pragma unroll
        for (int k = 0; k < DB_; k++) h[k] += xv * sw[j * DB_ + k];
    }
    float4* op = (float4*)(out + (size_t)(base + r) * DB_);
    op[0] = make_float4(h[0], h[1], h[2], h[3]);
    op[1] = make_float4(h[4], h[5], h[6], h[7]);
}

__global__ void __launch_bounds__(256) k_triplet(
    const float* __restrict__ hsbf, const float* __restrict__ wsbf2,
    const int* __restrict__ exp_kj, const int* __restrict__ red_ji,
    const float* __restrict__ down, float* __restrict__ agg, int T)
{
    __shared__ float sw[DB_ * DA_];
    for (int i = threadIdx.x; i < DB_ * DA_; i += 256) sw[i] = wsbf2[i];
    __syncthreads();

    const int q = threadIdx.x & 15;
    float w[DB_][4];
#pragma unroll
    for (int i = 0; i < DB_; i++)
#pragma unroll
        for (int j = 0; j < 4; j++) w[i][j] = sw[i * DA_ + q * 4 + j];

    int t = (blockIdx.x * blockDim.x + threadIdx.x) >> 4;
    const int stride = (gridDim.x * blockDim.x) >> 4;

    for (; t < T; t += stride) {
        int e = __ldg(exp_kj + t);
        int g = __ldg(red_ji + t);
        const float4* hp = (const float4*)(hsbf + (size_t)t * DB_);
        float4 h0 = __ldg(hp), h1 = __ldg(hp + 1);
        float hh[8] = {h0.x, h0.y, h0.z, h0.w, h1.x, h1.y, h1.z, h1.w};

        float s0 = 0.f, s1 = 0.f, s2 = 0.f, s3 = 0.f;
#pragma unroll
        for (int i = 0; i < DB_; i++) {
            s0 += hh[i] * w[i][0];
            s1 += hh[i] * w[i][1];
            s2 += hh[i] * w[i][2];
            s3 += hh[i] * w[i][3];
        }
        float4 a = __ldg((const float4*)(down + (size_t)e * DA_ + q * 4));
        float vx = a.x * s0, vy = a.y * s1, vz = a.z * s2, vw = a.w * s3;

        float* dst = agg + (size_t)g * DA_ + q * 4;
        asm volatile("red.global.add.v4.f32 [%0], {%1, %2, %3, %4};"
                     :: "l"(dst), "f"(vx), "f"(vy), "f"(vz), "f"(vw)
                     : "memory");
    }
}

// ---------------- launch -------------------------------------------------------
static inline int smem_sz(int KT, int NT) { return 4608 + KT * NT * 64 + 32768; }

extern "C" void kernel_launch(void* const* d_in, const int* in_sizes, int n_in,
                              void* d_out, int out_size)
{
    const float* m_input  = (const float*)d_in[0];
    const float* rbf      = (const float*)d_in[1];
    const float* sbf      = (const float*)d_in[2];
    const float* Wkj      = (const float*)d_in[3];
    const float* bkj      = (const float*)d_in[4];
    const float* Wrbf1    = (const float*)d_in[5];
    const float* Wrbf2    = (const float*)d_in[6];
    const float* Wdown    = (const float*)d_in[7];
    const float* Wsbf1    = (const float*)d_in[8];
    const float* Wsbf2    = (const float*)d_in[9];
    const float* Wup      = (const float*)d_in[10];
    const float* Wji      = (const float*)d_in[11];
    const float* bji      = (const float*)d_in[12];
    const float* rb1_W1   = (const float*)d_in[13];
    const float* rb1_b1   = (const float*)d_in[14];
    const float* rb1_W2   = (const float*)d_in[15];
    const float* rb1_b2   = (const float*)d_in[16];
    const float* Wfin     = (const float*)d_in[17];
    const float* bfin     = (const float*)d_in[18];
    const float* ra1_W1   = (const float*)d_in[19];
    const float* ra1_b1   = (const float*)d_in[20];
    const float* ra1_W2   = (const float*)d_in[21];
    const float* ra1_b2   = (const float*)d_in[22];
    const float* ra2_W1   = (const float*)d_in[23];
    const float* ra2_b1   = (const float*)d_in[24];
    const float* ra2_W2   = (const float*)d_in[25];
    const float* ra2_b2   = (const float*)d_in[26];
    const int*   red_ji   = (const int*)  d_in[27];
    const int*   exp_kj   = (const int*)  d_in[28];

    const int E = in_sizes[0] / D_;
    const int T = in_sizes[27];

    uint4 *fT1, *fM, *fX, *fMin, *fAgg;
    float *down, *agg, *wcomb, *hsbf;
    uint32_t *wf;
    cudaGetSymbolAddress((void**)&fT1,  g_fT1);
    cudaGetSymbolAddress((void**)&fM,   g_fM);
    cudaGetSymbolAddress((void**)&fX,   g_fX);
    cudaGetSymbolAddress((void**)&fMin, g_fMin);
    cudaGetSymbolAddress((void**)&fAgg, g_fAgg);
    cudaGetSymbolAddress((void**)&down, g_down);
    cudaGetSymbolAddress((void**)&agg,  g_agg);
    cudaGetSymbolAddress((void**)&wcomb, g_wcomb);
    cudaGetSymbolAddress((void**)&hsbf, g_hsbf);
    cudaGetSymbolAddress((void**)&wf,   g_wfrag);

    const size_t P8 = (size_t)RT_MAX * 8 * 32;
    const size_t P4 = (size_t)RT_MAX * 4 * 32;

    float* outp = (float*)d_out;
    const int grid = (E + 127) / 128;

    const int S_FF = smem_sz(8, 128);
    const int S_FD = smem_sz(8, 64);
    const int S_DF = smem_sz(4, 128);
    cudaFuncSetAttribute((const void*)gemm_mma<8,128,EP_SILU,true>,        cudaFuncAttributeMaxDynamicSharedMemorySize, S_FF);
    cudaFuncSetAttribute((const void*)gemm_mma<8,128,EP_SILU_ADDFR,true>,  cudaFuncAttributeMaxDynamicSharedMemorySize, S_FF);
    cudaFuncSetAttribute((const void*)gemm_mma<8,128,EP_SILU_ADDFR,false>, cudaFuncAttributeMaxDynamicSharedMemorySize, S_FF);
    cudaFuncSetAttribute((const void*)gemm_mma<8,128,EP_SILU_ADDF32,true>, cudaFuncAttributeMaxDynamicSharedMemorySize, S_FF);
    cudaFuncSetAttribute((const void*)gemm_mma<8,128,EP_SILU_MULRBF,true>, cudaFuncAttributeMaxDynamicSharedMemorySize, S_FF);
    cudaFuncSetAttribute((const void*)gemm_mma<8,64, EP_SILU,false>,       cudaFuncAttributeMaxDynamicSharedMemorySize, S_FD);
    cudaFuncSetAttribute((const void*)gemm_mma<4,128,EP_SILU_ADDFR,true>,  cudaFuncAttributeMaxDynamicSharedMemorySize, S_DF);

    cudaStream_t s2;
    cudaStreamCreateWithFlags(&s2, cudaStreamNonBlocking);
    cudaEvent_t evFork, evPrep, evJoin, evJoin2;
    cudaEventCreateWithFlags(&evFork, cudaEventDisableTiming);
    cudaEventCreateWithFlags(&evPrep, cudaEventDisableTiming);
    cudaEventCreateWithFlags(&evJoin, cudaEventDisableTiming);
    cudaEventCreateWithFlags(&evJoin2, cudaEventDisableTiming);

    // fork: s2 runs {zero(agg), hsbf}, then Wji GEMM (after main prep ready)
    cudaEventRecord(evFork, 0);
    cudaStreamWaitEvent(s2, evFork, 0);
    {
        int n4 = (E * DA_) / 4;
        k_zero<<<(n4 + 255) / 256, 256, 0, s2>>>((float4*)agg, n4);
    }
    k_hsbf<<<(T + 255) / 256, 256, 0, s2>>>(sbf, Wsbf1, hsbf, T);
    cudaEventRecord(evJoin, s2);

    // main stream prep
    k_wfrag_all<<<160, 256>>>(Wkj, Wji, rb1_W1, rb1_W2, Wfin,
                              ra1_W1, ra1_W2, ra2_W1, ra2_W2, Wdown, Wup, wf);
    k_wcomb<<<3, 256>>>(Wrbf1, Wrbf2, wcomb);
    {
        int nq = (E / 16) * 8 * 32;
        k_asplit<<<(nq + 255) / 256, 256>>>(m_input, E, 8, fMin, fMin + P8);
    }
    cudaEventRecord(evPrep, 0);

    // s2: fJi = silu(m_input @ Wji + bji)  -> fX planes (hides under triplet)
    cudaStreamWaitEvent(s2, evPrep, 0);
    gemm_mma<8,128,EP_SILU,true><<<grid, 256, S_FF, s2>>>(
        fMin, fMin + P8, wf + OFF_Wji, bji,
        nullptr, nullptr, nullptr, nullptr, nullptr,
        nullptr, fX, fX + P8, E);
    cudaEventRecord(evJoin2, s2);

    // 4. t1 = silu(m_input @ Wkj + bkj) * (rbf @ Wcomb)
    gemm_mma<8,128,EP_SILU_MULRBF,true><<<grid, 256, S_FF>>>(
        fMin, fMin + P8, wf + OFF_Wkj, bkj,
        nullptr, nullptr, nullptr, rbf, wcomb,
        nullptr, fT1, fT1 + P8, E);
    // 5. down = silu(t1 @ Wdown)
    gemm_mma<8,64,EP_SILU,false><<<grid, 256, S_FD>>>(
        fT1, fT1 + P8, wf + OFF_Wdown, nullptr,
        nullptr, nullptr, nullptr, nullptr, nullptr,
        down, nullptr, nullptr, E);

    // join: triplet needs hsbf + zeroed agg
    cudaStreamWaitEvent(0, evJoin, 0);

    // 6. triplet -> agg, split
    k_triplet<<<2048, 256>>>(hsbf, Wsbf2, exp_kj, red_ji, down, agg, T);
    {
        int nq = (E / 16) * 4 * 32;
        k_asplit<<<(nq + 255) / 256, 256>>>(agg, E, 4, fAgg, fAgg + P4);
    }

    // join: Wup epilogue needs fJi (fX)
    cudaStreamWaitEvent(0, evJoin2, 0);

    // 7+8. m = silu(agg @ Wup) + fJi  -> fM
    gemm_mma<4,128,EP_SILU_ADDFR,true><<<grid, 256, S_DF>>>(
        fAgg, fAgg + P4, wf + OFF_Wup, nullptr,
        fX, fX + P8, nullptr, nullptr, nullptr,
        nullptr, fM, fM + P8, E);
    // 9-10. residual block b1: fM -> fX
    gemm_mma<8,128,EP_SILU,true><<<grid, 256, S_FF>>>(
        fM, fM + P8, wf + OFF_rb1W1, rb1_b1,
        nullptr, nullptr, nullptr, nullptr, nullptr,
        nullptr, fT1, fT1 + P8, E);
    gemm_mma<8,128,EP_SILU_ADDFR,true><<<grid, 256, S_FF>>>(
        fT1, fT1 + P8, wf + OFF_rb1W2, rb1_b2,
        fM, fM + P8, nullptr, nullptr, nullptr,
        nullptr, fX, fX + P8, E);
    // 11. m = silu(fX @ Wfin + bfin) + m_input -> fM
    gemm_mma<8,128,EP_SILU_ADDF32,true><<<grid, 256, S_FF>>>(
        fX, fX + P8, wf + OFF_Wfin, bfin,
        nullptr, nullptr, m_input, nullptr, nullptr,
        nullptr, fM, fM + P8, E);
    // 12-13. residual block a1: fM -> fX
    gemm_mma<8,128,EP_SILU,true><<<grid, 256, S_FF>>>(
        fM, fM + P8, wf + OFF_ra1W1, ra1_b1,
        nullptr, nullptr, nullptr, nullptr, nullptr,
        nullptr, fT1, fT1 + P8, E);
    gemm_mma<8,128,EP_SILU_ADDFR,true><<<grid, 256, S_FF>>>(
        fT1, fT1 + P8, wf + OFF_ra1W2, ra1_b2,
        fM, fM + P8, nullptr, nullptr, nullptr,
        nullptr, fX, fX + P8, E);
    // 14-15. residual block a2: fX -> d_out
    gemm_mma<8,128,EP_SILU,true><<<grid, 256, S_FF>>>(
        fX, fX + P8, wf + OFF_ra2W1, ra2_b1,
        nullptr, nullptr, nullptr, nullptr, nullptr,
        nullptr, fT1, fT1 + P8, E);
    gemm_mma<8,128,EP_SILU_ADDFR,false><<<grid, 256, S_FF>>>(
        fT1, fT1 + P8, wf + OFF_ra2W2, ra2_b2,
        fX, fX + P8, nullptr, nullptr, nullptr,
        outp, nullptr, nullptr, E);

    cudaEventDestroy(evFork);
    cudaEventDestroy(evPrep);
    cudaEventDestroy(evJoin);
    cudaEventDestroy(evJoin2);
    cudaStreamDestroy(s2);
}